// round 13
// baseline (speedup 1.0000x reference)
#include <cuda_runtime.h>
#include <cuda_bf16.h>
#include <cstdint>

#define NN 50000
#define EE 800000
#define INC 256
#define HID 200
#define NPAD 50176              // 196 * 256
#define NFUSE 800               // 4 * HID
#define KEXT 768                // A_ext = [x_hi | x_hi | x_lo], B_ext = [W_hi; W_lo; W_hi]

// ---------------- scratch (static device globals; no allocations) ----------------
__device__ float g_Q1[NN * HID];
__device__ __nv_bfloat16 g_KV1[(size_t)NN * 400];   // [node][K(200) | V(200)] bf16
__device__ float g_S1[NN * HID];
__device__ float g_h1[NN * HID];
__device__ float g_b2[NN * 8];
__device__ int   g_deg[NN];
__device__ int   g_cur[NN];
__device__ int   g_rowptr[NN + 1];
__device__ int   g_csrc[EE];
__device__ __nv_bfloat16 g_xext[(size_t)NPAD * KEXT];   // [row][hi(256)|hi(256)|lo(256)]
__device__ __nv_bfloat16 g_Bt[(size_t)NFUSE * KEXT];

// ---------------- PTX helpers (compute_100-safe) ----------------
__device__ __forceinline__ uint32_t smem_u32(const void* p) {
    uint32_t a;
    asm("{ .reg .u64 t; cvta.to.shared.u64 t, %1; cvt.u32.u64 %0, t; }" : "=r"(a) : "l"(p));
    return a;
}
__device__ __forceinline__ void cpasync16(uint32_t dst, const void* src) {
    asm volatile("cp.async.cg.shared.global [%0], [%1], 16;" :: "r"(dst), "l"(src));
}
#define CP_COMMIT() asm volatile("cp.async.commit_group;" ::: "memory")
#define CP_WAIT(n)  asm volatile("cp.async.wait_group %0;" :: "n"(n) : "memory")

__device__ __forceinline__ void ldmx4(uint32_t& r0, uint32_t& r1, uint32_t& r2, uint32_t& r3,
                                      uint32_t addr) {
    asm volatile("ldmatrix.sync.aligned.m8n8.x4.shared.b16 {%0,%1,%2,%3}, [%4];"
                 : "=r"(r0), "=r"(r1), "=r"(r2), "=r"(r3) : "r"(addr));
}
__device__ __forceinline__ void ldmx2(uint32_t& r0, uint32_t& r1, uint32_t addr) {
    asm volatile("ldmatrix.sync.aligned.m8n8.x2.shared.b16 {%0,%1}, [%2];"
                 : "=r"(r0), "=r"(r1) : "r"(addr));
}
__device__ __forceinline__ void mma16816(float* d, const uint32_t* a, uint32_t b0, uint32_t b1) {
    asm volatile(
        "mma.sync.aligned.m16n8k16.row.col.f32.bf16.bf16.f32 "
        "{%0,%1,%2,%3}, {%4,%5,%6,%7}, {%8,%9}, {%0,%1,%2,%3};"
        : "+f"(d[0]), "+f"(d[1]), "+f"(d[2]), "+f"(d[3])
        : "r"(a[0]), "r"(a[1]), "r"(a[2]), "r"(a[3]), "r"(b0), "r"(b1));
}

// ---------------- CSR build ----------------
__global__ void zero_deg_kernel() {
    int i = blockIdx.x * blockDim.x + threadIdx.x;
    if (i < NN) g_deg[i] = 0;
}
__global__ void count_kernel(const int* __restrict__ ei) {
    int e = blockIdx.x * blockDim.x + threadIdx.x;
    if (e < EE) atomicAdd(&g_deg[ei[EE + e]], 1);
}
__global__ void scan_kernel() {
    __shared__ int part[1024];
    int tid = threadIdx.x;
    const int CH = (NN + 1023) / 1024;
    int b = tid * CH;
    int e = b + CH; if (e > NN) e = NN;
    int s = 0;
    for (int i = b; i < e && i < NN; i++) s += g_deg[i];
    part[tid] = s;
    __syncthreads();
    for (int off = 1; off < 1024; off <<= 1) {
        int v = part[tid];
        int add = (tid >= off) ? part[tid - off] : 0;
        __syncthreads();
        part[tid] = v + add;
        __syncthreads();
    }
    int run = (tid == 0) ? 0 : part[tid - 1];
    for (int i = b; i < e && i < NN; i++) {
        g_rowptr[i] = run;
        g_cur[i] = run;
        run += g_deg[i];
    }
    if (tid == 0) g_rowptr[NN] = part[1023];
}
__global__ void scatter_kernel(const int* __restrict__ ei) {
    int e = blockIdx.x * blockDim.x + threadIdx.x;
    if (e < EE) {
        int p = atomicAdd(&g_cur[ei[EE + e]], 1);
        g_csrc[p] = ei[e];
    }
}

// ---------------- bf16 split prep ----------------
__global__ void prep_x_kernel(const float* __restrict__ x) {
    int idx = blockIdx.x * blockDim.x + threadIdx.x;   // NPAD*64 threads
    if (idx >= NPAD * 64) return;
    int row = idx >> 6, c4 = (idx & 63) << 2;
    float4 v = make_float4(0.f, 0.f, 0.f, 0.f);
    if (row < NN) v = *(const float4*)(x + (size_t)row * INC + c4);
    float vv[4] = {v.x, v.y, v.z, v.w};
    __nv_bfloat16 h[4], l[4];
#pragma unroll
    for (int i = 0; i < 4; i++) {
        h[i] = __float2bfloat16(vv[i]);
        l[i] = __float2bfloat16(vv[i] - __bfloat162float(h[i]));
    }
    size_t o = (size_t)row * KEXT + c4;
    __nv_bfloat162 t0, t1, u0, u1;
    t0.x = h[0]; t0.y = h[1]; t1.x = h[2]; t1.y = h[3];
    u0.x = l[0]; u0.y = l[1]; u1.x = l[2]; u1.y = l[3];
    *(__nv_bfloat162*)(g_xext + o)           = t0;
    *(__nv_bfloat162*)(g_xext + o + 2)       = t1;
    *(__nv_bfloat162*)(g_xext + o + 256)     = t0;
    *(__nv_bfloat162*)(g_xext + o + 258)     = t1;
    *(__nv_bfloat162*)(g_xext + o + 512)     = u0;
    *(__nv_bfloat162*)(g_xext + o + 514)     = u1;
}

__global__ void prep_B_kernel(
    const float* __restrict__ Wq, const float* __restrict__ Wk,
    const float* __restrict__ Wv, const float* __restrict__ Ws)
{
    int idx = blockIdx.x * blockDim.x + threadIdx.x;   // 256*800 threads
    if (idx >= INC * NFUSE) return;
    int kk = idx / NFUSE, n = idx % NFUSE;
    int m = n / HID, jj = n % HID;
    const float* W = (m == 0) ? Wq : (m == 1) ? Wk : (m == 2) ? Wv : Ws;
    float w = W[(size_t)kk * HID + jj];
    __nv_bfloat16 h = __float2bfloat16(w);
    __nv_bfloat16 l = __float2bfloat16(w - __bfloat162float(h));
    size_t base = (size_t)n * KEXT;
    g_Bt[base + kk]       = h;
    g_Bt[base + 256 + kk] = l;
    g_Bt[base + 512 + kk] = h;
}

// ---------------- HMMA GEMM: [Q1|K1|V1|S1](+bias) = A_ext @ B_ext^T -------------
#define GM 256
#define GN 160
#define GK 64
#define NITER (KEXT / GK)   // 12

#define ASTAGE 32768
#define BSTAGE 20480
#define NSTAGE 3
#define OFF_BIAS 0
#define OFF_A    1024
#define OFF_B    (1024 + NSTAGE * ASTAGE)
#define GSMEM_BYTES (OFF_B + NSTAGE * BSTAGE) // 160768

__device__ __forceinline__ uint32_t swz(int r, int c) {   // byte offset in a stage, c in 0..7
    return (uint32_t)(r * 128 + (((c ^ r) & 7) << 4) + ((c & ~7) << 4));
}

__global__ __launch_bounds__(512, 1) void gemm1_tc(
    const float* __restrict__ bq, const float* __restrict__ bk,
    const float* __restrict__ bv, const float* __restrict__ bs)
{
    extern __shared__ char smem[];
    const uint32_t sb = smem_u32(smem);
    const int tid  = threadIdx.x;
    const int wid  = tid >> 5;
    const int lane = tid & 31;
    const int warpm = wid & 3;
    const int warpn = wid >> 2;
    const int r0 = blockIdx.y * GM;
    const int c0 = blockIdx.x * GN;

    if (tid < GN) {
        int cg = c0 + tid;
        int m = cg / HID, jj = cg - m * HID;
        const float* bp = (m == 0) ? bq : (m == 1) ? bk : (m == 2) ? bv : bs;
        *(float*)(smem + OFF_BIAS + tid * 4) = bp[jj];
    }

    const int lr = tid >> 3, lc = tid & 7;
    const uint32_t sdA0 = swz(lr,       lc);
    const uint32_t sdA1 = swz(lr + 64,  lc);
    const uint32_t sdA2 = swz(lr + 128, lc);
    const uint32_t sdA3 = swz(lr + 192, lc);
    const uint32_t sdB0 = sdA0;
    const uint32_t sdB1 = sdA1;
    const uint32_t sdB2 = swz(lr + 128, lc);
    const __nv_bfloat16* aptr0 = g_xext + (size_t)(r0 + lr) * KEXT + lc * 8;
    const __nv_bfloat16* aptr1 = aptr0 + (size_t)64  * KEXT;
    const __nv_bfloat16* aptr2 = aptr0 + (size_t)128 * KEXT;
    const __nv_bfloat16* aptr3 = aptr0 + (size_t)192 * KEXT;
    const __nv_bfloat16* bptr0 = g_Bt + (size_t)(c0 + lr) * KEXT + lc * 8;
    const __nv_bfloat16* bptr1 = bptr0 + (size_t)64  * KEXT;
    const __nv_bfloat16* bptr2 = bptr0 + (size_t)128 * KEXT;

    auto load_stage = [&](int sidx) {
        const uint32_t Ab = sb + OFF_A + sidx * ASTAGE;
        const uint32_t Bb = sb + OFF_B + sidx * BSTAGE;
        cpasync16(Ab + sdA0, aptr0);
        cpasync16(Ab + sdA1, aptr1);
        cpasync16(Ab + sdA2, aptr2);
        cpasync16(Ab + sdA3, aptr3);
        cpasync16(Bb + sdB0, bptr0);
        cpasync16(Bb + sdB1, bptr1);
        if (tid < 256) cpasync16(Bb + sdB2, bptr2);
        CP_COMMIT();
        aptr0 += GK; aptr1 += GK; aptr2 += GK; aptr3 += GK;
        bptr0 += GK; bptr1 += GK; bptr2 += GK;
    };

    float acc[4][5][4];
#pragma unroll
    for (int mt = 0; mt < 4; mt++)
#pragma unroll
        for (int nt = 0; nt < 5; nt++)
#pragma unroll
            for (int q = 0; q < 4; q++) acc[mt][nt][q] = 0.f;

    load_stage(0);
    load_stage(1);

    const int m0 = warpm * 64;
    const int n0 = warpn * 40;
    const int lrow = lane & 15;
    const int lchunk = lane >> 4;

    for (int j = 0; j < NITER; j += NSTAGE) {
#pragma unroll
        for (int s = 0; s < NSTAGE; s++) {
            const int i = j + s;
            if (i + 1 < NITER) { CP_WAIT(1); } else { CP_WAIT(0); }
            __syncthreads();
            if (i + 2 < NITER) load_stage((s + 2) % 3);

            const uint32_t Ab = sb + OFF_A + s * ASTAGE;
            const uint32_t Bb = sb + OFF_B + s * BSTAGE;
#pragma unroll
            for (int kt = 0; kt < 4; kt++) {
                const int cbase = kt * 2 + lchunk;
                uint32_t a[4][4];
#pragma unroll
                for (int mt = 0; mt < 4; mt++)
                    ldmx4(a[mt][0], a[mt][1], a[mt][2], a[mt][3],
                          Ab + swz(m0 + mt * 16 + lrow, cbase));
                uint32_t b[5][2];
#pragma unroll
                for (int p = 0; p < 2; p++) {
                    uint32_t q0, q1, q2, q3;
                    ldmx4(q0, q1, q2, q3, Bb + swz(n0 + p * 16 + lrow, cbase));
                    b[2 * p][0] = q0; b[2 * p + 1][0] = q1;
                    b[2 * p][1] = q2; b[2 * p + 1][1] = q3;
                }
                ldmx2(b[4][0], b[4][1],
                      Bb + swz(n0 + 32 + (lane & 7), kt * 2 + ((lane >> 3) & 1)));
#pragma unroll
                for (int mt = 0; mt < 4; mt++)
#pragma unroll
                    for (int nt = 0; nt < 5; nt++)
                        mma16816(acc[mt][nt], a[mt], b[nt][0], b[nt][1]);
            }
        }
    }

    // ---- epilogue: fused bias; Q/S fp32, K/V bf16x2 into g_KV1 ----
#pragma unroll
    for (int mt = 0; mt < 4; mt++) {
#pragma unroll
        for (int h = 0; h < 2; h++) {
            int gr = r0 + m0 + mt * 16 + h * 8 + (lane >> 2);
            if (gr >= NN) continue;
#pragma unroll
            for (int nt = 0; nt < 5; nt++) {
                int jl = n0 + nt * 8 + (lane & 3) * 2;
                int cg = c0 + jl;
                int m = cg / HID, jj = cg - m * HID;
                float2 bb = *(const float2*)(smem + OFF_BIAS + jl * 4);
                float2 v;
                v.x = acc[mt][nt][2 * h]     + bb.x;
                v.y = acc[mt][nt][2 * h + 1] + bb.y;
                if (m == 0)      *(float2*)(g_Q1 + (size_t)gr * HID + jj) = v;
                else if (m == 3) *(float2*)(g_S1 + (size_t)gr * HID + jj) = v;
                else {
                    __nv_bfloat162 t;
                    t.x = __float2bfloat16(v.x);
                    t.y = __float2bfloat16(v.y);
                    int off = (m == 1) ? jj : 200 + jj;
                    *(__nv_bfloat162*)(g_KV1 + (size_t)gr * 400 + off) = t;
                }
            }
        }
    }
}

// ---------------- layer-1 edge aggregation: warp per dst, 4-edge batch ---------
__global__ __launch_bounds__(256) void edge1_kernel() {
    int warp = (blockIdx.x * blockDim.x + threadIdx.x) >> 5;
    int lane = threadIdx.x & 31;
    if (warp >= NN) return;

    const int e0 = g_rowptr[warp];
    const int e1 = g_rowptr[warp + 1];
    const float scale = 0.0707106781186547f;  // 1/sqrt(200)

    float2 q[4];
#pragma unroll
    for (int r = 0; r < 4; r++) {
        int idx = lane + 32 * r;
        if (idx < 100) {
            float2 t = ((const float2*)(g_Q1 + (size_t)warp * HID))[idx];
            q[r].x = t.x * scale; q[r].y = t.y * scale;
        } else { q[r].x = 0.f; q[r].y = 0.f; }
    }

    float2 acc[4];
#pragma unroll
    for (int r = 0; r < 4; r++) { acc[r].x = 0.f; acc[r].y = 0.f; }
    float m = __int_as_float(0xff800000);
    float s = 0.f;

    int e = e0;
    for (; e + 4 <= e1; e += 4) {
        int si[4];
#pragma unroll
        for (int t = 0; t < 4; t++) si[t] = g_csrc[e + t];
        float2 kk[4][4], vv[4][4];
#pragma unroll
        for (int t = 0; t < 4; t++) {
            const __nv_bfloat162* p = (const __nv_bfloat162*)(g_KV1 + (size_t)si[t] * 400);
#pragma unroll
            for (int r = 0; r < 4; r++) {
                int idx = lane + 32 * r;
                bool ok = (idx < 100);
                kk[t][r] = ok ? __bfloat1622float2(p[idx])       : make_float2(0.f, 0.f);
                vv[t][r] = ok ? __bfloat1622float2(p[100 + idx]) : make_float2(0.f, 0.f);
            }
        }
        float p4[4];
#pragma unroll
        for (int t = 0; t < 4; t++) {
            float d = 0.f;
#pragma unroll
            for (int r = 0; r < 4; r++) d += q[r].x * kk[t][r].x + q[r].y * kk[t][r].y;
            p4[t] = d;
        }
#pragma unroll
        for (int off = 16; off > 0; off >>= 1)
#pragma unroll
            for (int t = 0; t < 4; t++)
                p4[t] += __shfl_xor_sync(0xffffffffu, p4[t], off);

        float mx = fmaxf(fmaxf(p4[0], p4[1]), fmaxf(p4[2], p4[3]));
        float mn = fmaxf(m, mx);
        float c = __expf(m - mn);
        float w[4];
#pragma unroll
        for (int t = 0; t < 4; t++) w[t] = __expf(p4[t] - mn);
        s = s * c + w[0] + w[1] + w[2] + w[3];
#pragma unroll
        for (int r = 0; r < 4; r++) {
            float ax = acc[r].x * c, ay = acc[r].y * c;
#pragma unroll
            for (int t = 0; t < 4; t++) { ax += w[t] * vv[t][r].x; ay += w[t] * vv[t][r].y; }
            acc[r].x = ax; acc[r].y = ay;
        }
        m = mn;
    }
    for (; e < e1; e++) {
        int src = g_csrc[e];
        const __nv_bfloat162* kvp = (const __nv_bfloat162*)(g_KV1 + (size_t)src * 400);
        float2 kv[4], vv[4];
#pragma unroll
        for (int r = 0; r < 4; r++) {
            int idx = lane + 32 * r;
            bool ok = (idx < 100);
            kv[r] = ok ? __bfloat1622float2(kvp[idx])       : make_float2(0.f, 0.f);
            vv[r] = ok ? __bfloat1622float2(kvp[100 + idx]) : make_float2(0.f, 0.f);
        }
        float p = 0.f;
#pragma unroll
        for (int r = 0; r < 4; r++) p += q[r].x * kv[r].x + q[r].y * kv[r].y;
#pragma unroll
        for (int off = 16; off > 0; off >>= 1)
            p += __shfl_xor_sync(0xffffffffu, p, off);
        float mn = fmaxf(m, p);
        float c = __expf(m - mn);
        float w = __expf(p - mn);
        s = s * c + w;
#pragma unroll
        for (int r = 0; r < 4; r++) {
            acc[r].x = acc[r].x * c + w * vv[r].x;
            acc[r].y = acc[r].y * c + w * vv[r].y;
        }
        m = mn;
    }

    float inv = (e1 > e0) ? (1.f / s) : 0.f;
#pragma unroll
    for (int r = 0; r < 4; r++) {
        int idx = lane + 32 * r;
        if (idx < 100) {
            float2 sk = ((const float2*)(g_S1 + (size_t)warp * HID))[idx];
            float2 o;
            o.x = acc[r].x * inv + sk.x;
            o.y = acc[r].y * inv + sk.y;
            o.x = o.x > 0.f ? o.x : 0.f;
            o.y = o.y > 0.f ? o.y : 0.f;
            ((float2*)(g_h1 + (size_t)warp * HID))[idx] = o;
        }
    }
}

// ---------------- layer-2 projections: warp per node (coalesced) ----------------
__global__ __launch_bounds__(256) void qkv2_kernel(
    const float* __restrict__ Wq, const float* __restrict__ bq,
    const float* __restrict__ Wk, const float* __restrict__ bk,
    const float* __restrict__ Wv, const float* __restrict__ bv,
    const float* __restrict__ Ws, const float* __restrict__ bs)
{
    __shared__ float ws[8][HID];   // transposed: ws[c][k]
    __shared__ float bb[8];
    for (int l = threadIdx.x; l < HID * 8; l += blockDim.x) {
        int c = l / HID, k = l - c * HID;
        int w = c >> 1, j = c & 1;
        const float* W = (w == 0) ? Wq : (w == 1) ? Wk : (w == 2) ? Wv : Ws;
        ws[c][k] = W[k * 2 + j];
    }
    if (threadIdx.x < 8) {
        int c = threadIdx.x, w = c >> 1, j = c & 1;
        const float* B = (w == 0) ? bq : (w == 1) ? bk : (w == 2) ? bv : bs;
        bb[c] = B[j];
    }
    __syncthreads();

    int warp = blockIdx.x * 8 + (threadIdx.x >> 5);
    int lane = threadIdx.x & 31;
    if (warp >= NN) return;

    const float* h = g_h1 + (size_t)warp * HID;
    float a[8];
#pragma unroll
    for (int c = 0; c < 8; c++) a[c] = 0.f;
#pragma unroll
    for (int r = 0; r < 7; r++) {
        int d = lane + 32 * r;
        if (d < HID) {
            float hv = h[d];
#pragma unroll
            for (int c = 0; c < 8; c++) a[c] += hv * ws[c][d];
        }
    }
#pragma unroll
    for (int off = 16; off > 0; off >>= 1)
#pragma unroll
        for (int c = 0; c < 8; c++)
            a[c] += __shfl_xor_sync(0xffffffffu, a[c], off);

    if (lane == 0) {
        float4 o0, o1;
        o0.x = a[0] + bb[0]; o0.y = a[1] + bb[1]; o0.z = a[2] + bb[2]; o0.w = a[3] + bb[3];
        o1.x = a[4] + bb[4]; o1.y = a[5] + bb[5]; o1.z = a[6] + bb[6]; o1.w = a[7] + bb[7];
        *(float4*)(g_b2 + (size_t)warp * 8)     = o0;
        *(float4*)(g_b2 + (size_t)warp * 8 + 4) = o1;
    }
}

// ---------------- layer-2 edge aggregation ----------------
__global__ __launch_bounds__(256) void edge2_kernel(float* __restrict__ out) {
    int i = blockIdx.x * blockDim.x + threadIdx.x;
    if (i >= NN) return;
    const int e0 = g_rowptr[i];
    const int e1 = g_rowptr[i + 1];
    const float scale = 0.7071067811865475f;
    const float* me = g_b2 + (size_t)i * 8;
    float q0 = me[0] * scale, q1 = me[1] * scale;
    float m = __int_as_float(0xff800000);
    float s = 0.f, a0 = 0.f, a1 = 0.f;
    for (int e = e0; e < e1; e++) {
        int src = g_csrc[e];
        const float* p = g_b2 + (size_t)src * 8;
        float k0 = p[2], k1 = p[3], v0 = p[4], v1 = p[5];
        float sc = q0 * k0 + q1 * k1;
        float mn = fmaxf(m, sc);
        float c = __expf(m - mn);
        float w = __expf(sc - mn);
        s = s * c + w;
        a0 = a0 * c + w * v0;
        a1 = a1 * c + w * v1;
        m = mn;
    }
    float inv = (e1 > e0) ? (1.f / s) : 0.f;
    float o0 = a0 * inv + me[6];
    float o1 = a1 * inv + me[7];
    out[(size_t)i * 2 + 0] = o0 > 0.f ? o0 : 0.f;
    out[(size_t)i * 2 + 1] = o1 > 0.f ? o1 : 0.f;
}

// ---------------- launch ----------------
extern "C" void kernel_launch(void* const* d_in, const int* in_sizes, int n_in,
                              void* d_out, int out_size) {
    const float* x   = (const float*)d_in[0];
    const int*   ei  = (const int*)d_in[1];
    const float *Wq1 = (const float*)d_in[2],  *bq1 = (const float*)d_in[3];
    const float *Wk1 = (const float*)d_in[4],  *bk1 = (const float*)d_in[5];
    const float *Wv1 = (const float*)d_in[6],  *bv1 = (const float*)d_in[7];
    const float *Ws1 = (const float*)d_in[8],  *bs1 = (const float*)d_in[9];
    const float *Wq2 = (const float*)d_in[10], *bq2 = (const float*)d_in[11];
    const float *Wk2 = (const float*)d_in[12], *bk2 = (const float*)d_in[13];
    const float *Wv2 = (const float*)d_in[14], *bv2 = (const float*)d_in[15];
    const float *Ws2 = (const float*)d_in[16], *bs2 = (const float*)d_in[17];
    float* out = (float*)d_out;

    // idempotent, deterministic, capture-safe
    cudaFuncSetAttribute(gemm1_tc, cudaFuncAttributeMaxDynamicSharedMemorySize, GSMEM_BYTES);

    // launch index 3 = gemm1_tc (ncu captures the 4th launch)
    prep_x_kernel<<<(NPAD * 64 + 255) / 256, 256>>>(x);                       // 0
    prep_B_kernel<<<(INC * NFUSE + 255) / 256, 256>>>(Wq1, Wk1, Wv1, Ws1);    // 1
    zero_deg_kernel<<<(NN + 255) / 256, 256>>>();                             // 2

    dim3 g1(NFUSE / GN, NPAD / GM);   // (5, 196)
    gemm1_tc<<<g1, 512, GSMEM_BYTES>>>(bq1, bk1, bv1, bs1);                   // 3 <- profiled

    count_kernel<<<(EE + 255) / 256, 256>>>(ei);                              // 4
    scan_kernel<<<1, 1024>>>();                                               // 5
    scatter_kernel<<<(EE + 255) / 256, 256>>>(ei);                            // 6

    edge1_kernel<<<(NN * 32 + 255) / 256, 256>>>();                           // 7
    qkv2_kernel<<<(NN * 32 + 255) / 256, 256>>>(Wq2, bq2, Wk2, bk2, Wv2, bv2, Ws2, bs2); // 8
    edge2_kernel<<<(NN + 255) / 256, 256>>>(out);                             // 9
}

// round 14
// speedup vs baseline: 1.1709x; 1.1709x over previous
#include <cuda_runtime.h>
#include <cuda_bf16.h>
#include <cstdint>

#define NN 50000
#define EE 800000
#define INC 256
#define HID 200
#define NPAD 50176              // 196 * 256
#define NFUSE 800               // 4 * HID
#define KEXT 768                // A_ext = [x_hi | x_hi | x_lo], B_ext = [W_hi; W_lo; W_hi]
#define SCAN_BLOCKS 196         // 196 * 256 = 50176 >= NN

// ---------------- scratch (static device globals; no allocations) ----------------
__device__ float g_Q1[NN * HID];
__device__ __nv_bfloat16 g_KV1[(size_t)NN * 400];   // [node][K(200) | V(200)] bf16
__device__ float g_S1[NN * HID];
__device__ float g_h1[NN * HID];
__device__ float g_b2[NN * 8];
__device__ int   g_deg[NN];
__device__ int   g_cur[NN];
__device__ int   g_rowptr[NN + 1];
__device__ int   g_csrc[EE];
__device__ int   g_bsum[SCAN_BLOCKS];
__device__ __nv_bfloat16 g_xext[(size_t)NPAD * KEXT];   // [row][hi(256)|hi(256)|lo(256)]
__device__ __nv_bfloat16 g_Bt[(size_t)NFUSE * KEXT];

// ---------------- PTX helpers (compute_100-safe) ----------------
__device__ __forceinline__ uint32_t smem_u32(const void* p) {
    uint32_t a;
    asm("{ .reg .u64 t; cvta.to.shared.u64 t, %1; cvt.u32.u64 %0, t; }" : "=r"(a) : "l"(p));
    return a;
}
__device__ __forceinline__ void cpasync16(uint32_t dst, const void* src) {
    asm volatile("cp.async.cg.shared.global [%0], [%1], 16;" :: "r"(dst), "l"(src));
}
#define CP_COMMIT() asm volatile("cp.async.commit_group;" ::: "memory")
#define CP_WAIT(n)  asm volatile("cp.async.wait_group %0;" :: "n"(n) : "memory")

__device__ __forceinline__ void ldmx4(uint32_t& r0, uint32_t& r1, uint32_t& r2, uint32_t& r3,
                                      uint32_t addr) {
    asm volatile("ldmatrix.sync.aligned.m8n8.x4.shared.b16 {%0,%1,%2,%3}, [%4];"
                 : "=r"(r0), "=r"(r1), "=r"(r2), "=r"(r3) : "r"(addr));
}
__device__ __forceinline__ void ldmx2(uint32_t& r0, uint32_t& r1, uint32_t addr) {
    asm volatile("ldmatrix.sync.aligned.m8n8.x2.shared.b16 {%0,%1}, [%2];"
                 : "=r"(r0), "=r"(r1) : "r"(addr));
}
__device__ __forceinline__ void mma16816(float* d, const uint32_t* a, uint32_t b0, uint32_t b1) {
    asm volatile(
        "mma.sync.aligned.m16n8k16.row.col.f32.bf16.bf16.f32 "
        "{%0,%1,%2,%3}, {%4,%5,%6,%7}, {%8,%9}, {%0,%1,%2,%3};"
        : "+f"(d[0]), "+f"(d[1]), "+f"(d[2]), "+f"(d[3])
        : "r"(a[0]), "r"(a[1]), "r"(a[2]), "r"(a[3]), "r"(b0), "r"(b1));
}

// ---------------- CSR build ----------------
__global__ void zero_deg_kernel() {
    int i = blockIdx.x * blockDim.x + threadIdx.x;
    if (i < NN) g_deg[i] = 0;
}
__global__ void count_kernel(const int* __restrict__ ei) {
    int e = blockIdx.x * blockDim.x + threadIdx.x;
    if (e < EE) atomicAdd(&g_deg[ei[EE + e]], 1);
}

// coalesced 3-phase scan
__global__ void scan1_kernel() {
    __shared__ int sm[256];
    int tid = threadIdx.x;
    int i = blockIdx.x * 256 + tid;
    int v = (i < NN) ? g_deg[i] : 0;
    sm[tid] = v;
    __syncthreads();
#pragma unroll
    for (int off = 1; off < 256; off <<= 1) {
        int t = sm[tid];
        int a = (tid >= off) ? sm[tid - off] : 0;
        __syncthreads();
        sm[tid] = t + a;
        __syncthreads();
    }
    if (i < NN) g_rowptr[i] = sm[tid] - v;          // exclusive within block
    if (tid == 255) g_bsum[blockIdx.x] = sm[255];   // block total
}
__global__ void scan2_kernel() {
    __shared__ int sm[256];
    int tid = threadIdx.x;
    int v = (tid < SCAN_BLOCKS) ? g_bsum[tid] : 0;
    sm[tid] = v;
    __syncthreads();
#pragma unroll
    for (int off = 1; off < 256; off <<= 1) {
        int t = sm[tid];
        int a = (tid >= off) ? sm[tid - off] : 0;
        __syncthreads();
        sm[tid] = t + a;
        __syncthreads();
    }
    if (tid < SCAN_BLOCKS) g_bsum[tid] = sm[tid] - v;   // exclusive block offsets
    if (tid == 0) g_rowptr[NN] = EE;
}
__global__ void scan3_kernel() {
    int tid = threadIdx.x;
    int i = blockIdx.x * 256 + tid;
    if (i < NN) {
        int r = g_rowptr[i] + g_bsum[blockIdx.x];
        g_rowptr[i] = r;
        g_cur[i] = r;
    }
}

__global__ void scatter_kernel(const int* __restrict__ ei) {
    int e = blockIdx.x * blockDim.x + threadIdx.x;
    if (e < EE) {
        int p = atomicAdd(&g_cur[ei[EE + e]], 1);
        g_csrc[p] = ei[e];
    }
}

// ---------------- bf16 split prep ----------------
__global__ void prep_x_kernel(const float* __restrict__ x) {
    int idx = blockIdx.x * blockDim.x + threadIdx.x;   // NPAD*64 threads
    if (idx >= NPAD * 64) return;
    int row = idx >> 6, c4 = (idx & 63) << 2;
    float4 v = make_float4(0.f, 0.f, 0.f, 0.f);
    if (row < NN) v = *(const float4*)(x + (size_t)row * INC + c4);
    float vv[4] = {v.x, v.y, v.z, v.w};
    __nv_bfloat16 h[4], l[4];
#pragma unroll
    for (int i = 0; i < 4; i++) {
        h[i] = __float2bfloat16(vv[i]);
        l[i] = __float2bfloat16(vv[i] - __bfloat162float(h[i]));
    }
    size_t o = (size_t)row * KEXT + c4;
    __nv_bfloat162 t0, t1, u0, u1;
    t0.x = h[0]; t0.y = h[1]; t1.x = h[2]; t1.y = h[3];
    u0.x = l[0]; u0.y = l[1]; u1.x = l[2]; u1.y = l[3];
    *(__nv_bfloat162*)(g_xext + o)           = t0;
    *(__nv_bfloat162*)(g_xext + o + 2)       = t1;
    *(__nv_bfloat162*)(g_xext + o + 256)     = t0;
    *(__nv_bfloat162*)(g_xext + o + 258)     = t1;
    *(__nv_bfloat162*)(g_xext + o + 512)     = u0;
    *(__nv_bfloat162*)(g_xext + o + 514)     = u1;
}

__global__ void prep_B_kernel(
    const float* __restrict__ Wq, const float* __restrict__ Wk,
    const float* __restrict__ Wv, const float* __restrict__ Ws)
{
    int idx = blockIdx.x * blockDim.x + threadIdx.x;   // 256*800 threads
    if (idx >= INC * NFUSE) return;
    int kk = idx / NFUSE, n = idx % NFUSE;
    int m = n / HID, jj = n % HID;
    const float* W = (m == 0) ? Wq : (m == 1) ? Wk : (m == 2) ? Wv : Ws;
    float w = W[(size_t)kk * HID + jj];
    __nv_bfloat16 h = __float2bfloat16(w);
    __nv_bfloat16 l = __float2bfloat16(w - __bfloat162float(h));
    size_t base = (size_t)n * KEXT;
    g_Bt[base + kk]       = h;
    g_Bt[base + 256 + kk] = l;
    g_Bt[base + 512 + kk] = h;
}

// ---------------- HMMA GEMM: [Q1|K1|V1|S1](+bias) = A_ext @ B_ext^T -------------
#define GM 256
#define GN 160
#define GK 64
#define NITER (KEXT / GK)   // 12

#define ASTAGE 32768
#define BSTAGE 20480
#define NSTAGE 3
#define OFF_BIAS 0
#define OFF_A    1024
#define OFF_B    (1024 + NSTAGE * ASTAGE)
#define GSMEM_BYTES (OFF_B + NSTAGE * BSTAGE) // 160768

__device__ __forceinline__ uint32_t swz(int r, int c) {   // byte offset in a stage, c in 0..7
    return (uint32_t)(r * 128 + (((c ^ r) & 7) << 4) + ((c & ~7) << 4));
}

__global__ __launch_bounds__(512, 1) void gemm1_tc(
    const float* __restrict__ bq, const float* __restrict__ bk,
    const float* __restrict__ bv, const float* __restrict__ bs)
{
    extern __shared__ char smem[];
    const uint32_t sb = smem_u32(smem);
    const int tid  = threadIdx.x;
    const int wid  = tid >> 5;
    const int lane = tid & 31;
    const int warpm = wid & 3;
    const int warpn = wid >> 2;
    const int r0 = blockIdx.y * GM;
    const int c0 = blockIdx.x * GN;

    if (tid < GN) {
        int cg = c0 + tid;
        int m = cg / HID, jj = cg - m * HID;
        const float* bp = (m == 0) ? bq : (m == 1) ? bk : (m == 2) ? bv : bs;
        *(float*)(smem + OFF_BIAS + tid * 4) = bp[jj];
    }

    const int lr = tid >> 3, lc = tid & 7;
    const uint32_t sdA0 = swz(lr,       lc);
    const uint32_t sdA1 = swz(lr + 64,  lc);
    const uint32_t sdA2 = swz(lr + 128, lc);
    const uint32_t sdA3 = swz(lr + 192, lc);
    const uint32_t sdB0 = sdA0;
    const uint32_t sdB1 = sdA1;
    const uint32_t sdB2 = swz(lr + 128, lc);
    const __nv_bfloat16* aptr0 = g_xext + (size_t)(r0 + lr) * KEXT + lc * 8;
    const __nv_bfloat16* aptr1 = aptr0 + (size_t)64  * KEXT;
    const __nv_bfloat16* aptr2 = aptr0 + (size_t)128 * KEXT;
    const __nv_bfloat16* aptr3 = aptr0 + (size_t)192 * KEXT;
    const __nv_bfloat16* bptr0 = g_Bt + (size_t)(c0 + lr) * KEXT + lc * 8;
    const __nv_bfloat16* bptr1 = bptr0 + (size_t)64  * KEXT;
    const __nv_bfloat16* bptr2 = bptr0 + (size_t)128 * KEXT;

    auto load_stage = [&](int sidx) {
        const uint32_t Ab = sb + OFF_A + sidx * ASTAGE;
        const uint32_t Bb = sb + OFF_B + sidx * BSTAGE;
        cpasync16(Ab + sdA0, aptr0);
        cpasync16(Ab + sdA1, aptr1);
        cpasync16(Ab + sdA2, aptr2);
        cpasync16(Ab + sdA3, aptr3);
        cpasync16(Bb + sdB0, bptr0);
        cpasync16(Bb + sdB1, bptr1);
        if (tid < 256) cpasync16(Bb + sdB2, bptr2);
        CP_COMMIT();
        aptr0 += GK; aptr1 += GK; aptr2 += GK; aptr3 += GK;
        bptr0 += GK; bptr1 += GK; bptr2 += GK;
    };

    float acc[4][5][4];
#pragma unroll
    for (int mt = 0; mt < 4; mt++)
#pragma unroll
        for (int nt = 0; nt < 5; nt++)
#pragma unroll
            for (int q = 0; q < 4; q++) acc[mt][nt][q] = 0.f;

    load_stage(0);
    load_stage(1);

    const int m0 = warpm * 64;
    const int n0 = warpn * 40;
    const int lrow = lane & 15;
    const int lchunk = lane >> 4;

    for (int j = 0; j < NITER; j += NSTAGE) {
#pragma unroll
        for (int s = 0; s < NSTAGE; s++) {
            const int i = j + s;
            if (i + 1 < NITER) { CP_WAIT(1); } else { CP_WAIT(0); }
            __syncthreads();
            if (i + 2 < NITER) load_stage((s + 2) % 3);

            const uint32_t Ab = sb + OFF_A + s * ASTAGE;
            const uint32_t Bb = sb + OFF_B + s * BSTAGE;
#pragma unroll
            for (int kt = 0; kt < 4; kt++) {
                const int cbase = kt * 2 + lchunk;
                uint32_t a[4][4];
#pragma unroll
                for (int mt = 0; mt < 4; mt++)
                    ldmx4(a[mt][0], a[mt][1], a[mt][2], a[mt][3],
                          Ab + swz(m0 + mt * 16 + lrow, cbase));
                uint32_t b[5][2];
#pragma unroll
                for (int p = 0; p < 2; p++) {
                    uint32_t q0, q1, q2, q3;
                    ldmx4(q0, q1, q2, q3, Bb + swz(n0 + p * 16 + lrow, cbase));
                    b[2 * p][0] = q0; b[2 * p + 1][0] = q1;
                    b[2 * p][1] = q2; b[2 * p + 1][1] = q3;
                }
                ldmx2(b[4][0], b[4][1],
                      Bb + swz(n0 + 32 + (lane & 7), kt * 2 + ((lane >> 3) & 1)));
#pragma unroll
                for (int mt = 0; mt < 4; mt++)
#pragma unroll
                    for (int nt = 0; nt < 5; nt++)
                        mma16816(acc[mt][nt], a[mt], b[nt][0], b[nt][1]);
            }
        }
    }

    // ---- epilogue: fused bias; Q/S fp32, K/V bf16x2 into g_KV1 ----
#pragma unroll
    for (int mt = 0; mt < 4; mt++) {
#pragma unroll
        for (int h = 0; h < 2; h++) {
            int gr = r0 + m0 + mt * 16 + h * 8 + (lane >> 2);
            if (gr >= NN) continue;
#pragma unroll
            for (int nt = 0; nt < 5; nt++) {
                int jl = n0 + nt * 8 + (lane & 3) * 2;
                int cg = c0 + jl;
                int m = cg / HID, jj = cg - m * HID;
                float2 bb = *(const float2*)(smem + OFF_BIAS + jl * 4);
                float2 v;
                v.x = acc[mt][nt][2 * h]     + bb.x;
                v.y = acc[mt][nt][2 * h + 1] + bb.y;
                if (m == 0)      *(float2*)(g_Q1 + (size_t)gr * HID + jj) = v;
                else if (m == 3) *(float2*)(g_S1 + (size_t)gr * HID + jj) = v;
                else {
                    __nv_bfloat162 t;
                    t.x = __float2bfloat16(v.x);
                    t.y = __float2bfloat16(v.y);
                    int off = (m == 1) ? jj : 200 + jj;
                    *(__nv_bfloat162*)(g_KV1 + (size_t)gr * 400 + off) = t;
                }
            }
        }
    }
}

// ---------------- layer-1 edge aggregation: warp per dst, 4-edge batch ---------
__global__ __launch_bounds__(256) void edge1_kernel() {
    int warp = (blockIdx.x * blockDim.x + threadIdx.x) >> 5;
    int lane = threadIdx.x & 31;
    if (warp >= NN) return;

    const int e0 = g_rowptr[warp];
    const int e1 = g_rowptr[warp + 1];
    const float scale = 0.0707106781186547f;  // 1/sqrt(200)

    float2 q[4];
#pragma unroll
    for (int r = 0; r < 4; r++) {
        int idx = lane + 32 * r;
        if (idx < 100) {
            float2 t = ((const float2*)(g_Q1 + (size_t)warp * HID))[idx];
            q[r].x = t.x * scale; q[r].y = t.y * scale;
        } else { q[r].x = 0.f; q[r].y = 0.f; }
    }

    float2 acc[4];
#pragma unroll
    for (int r = 0; r < 4; r++) { acc[r].x = 0.f; acc[r].y = 0.f; }
    float m = __int_as_float(0xff800000);
    float s = 0.f;

    int e = e0;
    for (; e + 4 <= e1; e += 4) {
        int si[4];
#pragma unroll
        for (int t = 0; t < 4; t++) si[t] = g_csrc[e + t];
        float2 kk[4][4], vv[4][4];
#pragma unroll
        for (int t = 0; t < 4; t++) {
            const __nv_bfloat162* p = (const __nv_bfloat162*)(g_KV1 + (size_t)si[t] * 400);
#pragma unroll
            for (int r = 0; r < 4; r++) {
                int idx = lane + 32 * r;
                bool ok = (idx < 100);
                kk[t][r] = ok ? __bfloat1622float2(p[idx])       : make_float2(0.f, 0.f);
                vv[t][r] = ok ? __bfloat1622float2(p[100 + idx]) : make_float2(0.f, 0.f);
            }
        }
        float p4[4];
#pragma unroll
        for (int t = 0; t < 4; t++) {
            float d = 0.f;
#pragma unroll
            for (int r = 0; r < 4; r++) d += q[r].x * kk[t][r].x + q[r].y * kk[t][r].y;
            p4[t] = d;
        }
#pragma unroll
        for (int off = 16; off > 0; off >>= 1)
#pragma unroll
            for (int t = 0; t < 4; t++)
                p4[t] += __shfl_xor_sync(0xffffffffu, p4[t], off);

        float mx = fmaxf(fmaxf(p4[0], p4[1]), fmaxf(p4[2], p4[3]));
        float mn = fmaxf(m, mx);
        float c = __expf(m - mn);
        float w[4];
#pragma unroll
        for (int t = 0; t < 4; t++) w[t] = __expf(p4[t] - mn);
        s = s * c + w[0] + w[1] + w[2] + w[3];
#pragma unroll
        for (int r = 0; r < 4; r++) {
            float ax = acc[r].x * c, ay = acc[r].y * c;
#pragma unroll
            for (int t = 0; t < 4; t++) { ax += w[t] * vv[t][r].x; ay += w[t] * vv[t][r].y; }
            acc[r].x = ax; acc[r].y = ay;
        }
        m = mn;
    }
    for (; e < e1; e++) {
        int src = g_csrc[e];
        const __nv_bfloat162* kvp = (const __nv_bfloat162*)(g_KV1 + (size_t)src * 400);
        float2 kv[4], vv[4];
#pragma unroll
        for (int r = 0; r < 4; r++) {
            int idx = lane + 32 * r;
            bool ok = (idx < 100);
            kv[r] = ok ? __bfloat1622float2(kvp[idx])       : make_float2(0.f, 0.f);
            vv[r] = ok ? __bfloat1622float2(kvp[100 + idx]) : make_float2(0.f, 0.f);
        }
        float p = 0.f;
#pragma unroll
        for (int r = 0; r < 4; r++) p += q[r].x * kv[r].x + q[r].y * kv[r].y;
#pragma unroll
        for (int off = 16; off > 0; off >>= 1)
            p += __shfl_xor_sync(0xffffffffu, p, off);
        float mn = fmaxf(m, p);
        float c = __expf(m - mn);
        float w = __expf(p - mn);
        s = s * c + w;
#pragma unroll
        for (int r = 0; r < 4; r++) {
            acc[r].x = acc[r].x * c + w * vv[r].x;
            acc[r].y = acc[r].y * c + w * vv[r].y;
        }
        m = mn;
    }

    float inv = (e1 > e0) ? (1.f / s) : 0.f;
#pragma unroll
    for (int r = 0; r < 4; r++) {
        int idx = lane + 32 * r;
        if (idx < 100) {
            float2 sk = ((const float2*)(g_S1 + (size_t)warp * HID))[idx];
            float2 o;
            o.x = acc[r].x * inv + sk.x;
            o.y = acc[r].y * inv + sk.y;
            o.x = o.x > 0.f ? o.x : 0.f;
            o.y = o.y > 0.f ? o.y : 0.f;
            ((float2*)(g_h1 + (size_t)warp * HID))[idx] = o;
        }
    }
}

// ---------------- layer-2 projections: warp per node (coalesced) ----------------
__global__ __launch_bounds__(256) void qkv2_kernel(
    const float* __restrict__ Wq, const float* __restrict__ bq,
    const float* __restrict__ Wk, const float* __restrict__ bk,
    const float* __restrict__ Wv, const float* __restrict__ bv,
    const float* __restrict__ Ws, const float* __restrict__ bs)
{
    __shared__ float ws[8][HID];   // transposed: ws[c][k]
    __shared__ float bb[8];
    for (int l = threadIdx.x; l < HID * 8; l += blockDim.x) {
        int c = l / HID, k = l - c * HID;
        int w = c >> 1, j = c & 1;
        const float* W = (w == 0) ? Wq : (w == 1) ? Wk : (w == 2) ? Wv : Ws;
        ws[c][k] = W[k * 2 + j];
    }
    if (threadIdx.x < 8) {
        int c = threadIdx.x, w = c >> 1, j = c & 1;
        const float* B = (w == 0) ? bq : (w == 1) ? bk : (w == 2) ? bv : bs;
        bb[c] = B[j];
    }
    __syncthreads();

    int warp = blockIdx.x * 8 + (threadIdx.x >> 5);
    int lane = threadIdx.x & 31;
    if (warp >= NN) return;

    const float* h = g_h1 + (size_t)warp * HID;
    float a[8];
#pragma unroll
    for (int c = 0; c < 8; c++) a[c] = 0.f;
#pragma unroll
    for (int r = 0; r < 7; r++) {
        int d = lane + 32 * r;
        if (d < HID) {
            float hv = h[d];
#pragma unroll
            for (int c = 0; c < 8; c++) a[c] += hv * ws[c][d];
        }
    }
#pragma unroll
    for (int off = 16; off > 0; off >>= 1)
#pragma unroll
        for (int c = 0; c < 8; c++)
            a[c] += __shfl_xor_sync(0xffffffffu, a[c], off);

    if (lane == 0) {
        float4 o0, o1;
        o0.x = a[0] + bb[0]; o0.y = a[1] + bb[1]; o0.z = a[2] + bb[2]; o0.w = a[3] + bb[3];
        o1.x = a[4] + bb[4]; o1.y = a[5] + bb[5]; o1.z = a[6] + bb[6]; o1.w = a[7] + bb[7];
        *(float4*)(g_b2 + (size_t)warp * 8)     = o0;
        *(float4*)(g_b2 + (size_t)warp * 8 + 4) = o1;
    }
}

// ---------------- layer-2 edge aggregation ----------------
__global__ __launch_bounds__(256) void edge2_kernel(float* __restrict__ out) {
    int i = blockIdx.x * blockDim.x + threadIdx.x;
    if (i >= NN) return;
    const int e0 = g_rowptr[i];
    const int e1 = g_rowptr[i + 1];
    const float scale = 0.7071067811865475f;
    const float* me = g_b2 + (size_t)i * 8;
    float q0 = me[0] * scale, q1 = me[1] * scale;
    float m = __int_as_float(0xff800000);
    float s = 0.f, a0 = 0.f, a1 = 0.f;
    for (int e = e0; e < e1; e++) {
        int src = g_csrc[e];
        const float* p = g_b2 + (size_t)src * 8;
        float k0 = p[2], k1 = p[3], v0 = p[4], v1 = p[5];
        float sc = q0 * k0 + q1 * k1;
        float mn = fmaxf(m, sc);
        float c = __expf(m - mn);
        float w = __expf(sc - mn);
        s = s * c + w;
        a0 = a0 * c + w * v0;
        a1 = a1 * c + w * v1;
        m = mn;
    }
    float inv = (e1 > e0) ? (1.f / s) : 0.f;
    float o0 = a0 * inv + me[6];
    float o1 = a1 * inv + me[7];
    out[(size_t)i * 2 + 0] = o0 > 0.f ? o0 : 0.f;
    out[(size_t)i * 2 + 1] = o1 > 0.f ? o1 : 0.f;
}

// ---------------- launch ----------------
extern "C" void kernel_launch(void* const* d_in, const int* in_sizes, int n_in,
                              void* d_out, int out_size) {
    const float* x   = (const float*)d_in[0];
    const int*   ei  = (const int*)d_in[1];
    const float *Wq1 = (const float*)d_in[2],  *bq1 = (const float*)d_in[3];
    const float *Wk1 = (const float*)d_in[4],  *bk1 = (const float*)d_in[5];
    const float *Wv1 = (const float*)d_in[6],  *bv1 = (const float*)d_in[7];
    const float *Ws1 = (const float*)d_in[8],  *bs1 = (const float*)d_in[9];
    const float *Wq2 = (const float*)d_in[10], *bq2 = (const float*)d_in[11];
    const float *Wk2 = (const float*)d_in[12], *bk2 = (const float*)d_in[13];
    const float *Wv2 = (const float*)d_in[14], *bv2 = (const float*)d_in[15];
    const float *Ws2 = (const float*)d_in[16], *bs2 = (const float*)d_in[17];
    float* out = (float*)d_out;

    // idempotent, deterministic, capture-safe
    cudaFuncSetAttribute(gemm1_tc, cudaFuncAttributeMaxDynamicSharedMemorySize, GSMEM_BYTES);

    // launch index 3 = gemm1_tc (ncu captures the 4th launch)
    prep_x_kernel<<<(NPAD * 64 + 255) / 256, 256>>>(x);                       // 0
    prep_B_kernel<<<(INC * NFUSE + 255) / 256, 256>>>(Wq1, Wk1, Wv1, Ws1);    // 1
    zero_deg_kernel<<<(NN + 255) / 256, 256>>>();                             // 2

    dim3 g1(NFUSE / GN, NPAD / GM);   // (5, 196)
    gemm1_tc<<<g1, 512, GSMEM_BYTES>>>(bq1, bk1, bv1, bs1);                   // 3 <- profiled

    count_kernel<<<(EE + 255) / 256, 256>>>(ei);                              // 4
    scan1_kernel<<<SCAN_BLOCKS, 256>>>();                                     // 5
    scan2_kernel<<<1, 256>>>();                                               // 6
    scan3_kernel<<<SCAN_BLOCKS, 256>>>();                                     // 7
    scatter_kernel<<<(EE + 255) / 256, 256>>>(ei);                            // 8

    edge1_kernel<<<(NN * 32 + 255) / 256, 256>>>();                           // 9
    qkv2_kernel<<<(NN * 32 + 255) / 256, 256>>>(Wq2, bq2, Wk2, bk2, Wv2, bv2, Ws2, bs2); // 10
    edge2_kernel<<<(NN + 255) / 256, 256>>>(out);                             // 11
}

// round 15
// speedup vs baseline: 1.2173x; 1.0396x over previous
#include <cuda_runtime.h>
#include <cuda_bf16.h>
#include <cstdint>

#define NN 50000
#define EE 800000
#define INC 256
#define HID 200
#define NPAD 50176              // 196 * 256
#define NFUSE 800               // 4 * HID
#define KEXT 768                // A_ext = [x_hi | x_hi | x_lo], B_ext = [W_hi; W_lo; W_hi]
#define SCAN_BLOCKS 196         // 196 * 256 = 50176 >= NN

// ---------------- scratch (static device globals; no allocations) ----------------
__device__ float g_Q1[NN * HID];
__device__ __nv_bfloat16 g_KV1[(size_t)NN * 400];   // [node][K(200) | V(200)] bf16
__device__ float g_S1[NN * HID];
__device__ float g_h1[NN * HID];
__device__ float g_b2[NN * 8];
__device__ int   g_deg[NN];
__device__ int   g_cur[NN];
__device__ int   g_rowptr[NN + 1];
__device__ int   g_csrc[EE];
__device__ int   g_bsum[SCAN_BLOCKS];
__device__ __nv_bfloat16 g_xext[(size_t)NPAD * KEXT];   // [row][hi(256)|hi(256)|lo(256)]
__device__ __nv_bfloat16 g_Bt[(size_t)NFUSE * KEXT];

// ---------------- PTX helpers (compute_100-safe) ----------------
__device__ __forceinline__ uint32_t smem_u32(const void* p) {
    uint32_t a;
    asm("{ .reg .u64 t; cvta.to.shared.u64 t, %1; cvt.u32.u64 %0, t; }" : "=r"(a) : "l"(p));
    return a;
}
__device__ __forceinline__ void cpasync16(uint32_t dst, const void* src) {
    asm volatile("cp.async.cg.shared.global [%0], [%1], 16;" :: "r"(dst), "l"(src));
}
#define CP_COMMIT() asm volatile("cp.async.commit_group;" ::: "memory")
#define CP_WAIT(n)  asm volatile("cp.async.wait_group %0;" :: "n"(n) : "memory")

__device__ __forceinline__ void ldmx4(uint32_t& r0, uint32_t& r1, uint32_t& r2, uint32_t& r3,
                                      uint32_t addr) {
    asm volatile("ldmatrix.sync.aligned.m8n8.x4.shared.b16 {%0,%1,%2,%3}, [%4];"
                 : "=r"(r0), "=r"(r1), "=r"(r2), "=r"(r3) : "r"(addr));
}
__device__ __forceinline__ void ldmx2(uint32_t& r0, uint32_t& r1, uint32_t addr) {
    asm volatile("ldmatrix.sync.aligned.m8n8.x2.shared.b16 {%0,%1}, [%2];"
                 : "=r"(r0), "=r"(r1) : "r"(addr));
}
__device__ __forceinline__ void mma16816(float* d, const uint32_t* a, uint32_t b0, uint32_t b1) {
    asm volatile(
        "mma.sync.aligned.m16n8k16.row.col.f32.bf16.bf16.f32 "
        "{%0,%1,%2,%3}, {%4,%5,%6,%7}, {%8,%9}, {%0,%1,%2,%3};"
        : "+f"(d[0]), "+f"(d[1]), "+f"(d[2]), "+f"(d[3])
        : "r"(a[0]), "r"(a[1]), "r"(a[2]), "r"(a[3]), "r"(b0), "r"(b1));
}

// ---------------- CSR build ----------------
__global__ void zero_deg_kernel() {
    int i = blockIdx.x * blockDim.x + threadIdx.x;
    if (i < NN) g_deg[i] = 0;
}
__global__ void count_kernel(const int* __restrict__ ei) {
    int e = blockIdx.x * blockDim.x + threadIdx.x;
    if (e < EE) atomicAdd(&g_deg[ei[EE + e]], 1);
}

// coalesced 3-phase scan
__global__ void scan1_kernel() {
    __shared__ int sm[256];
    int tid = threadIdx.x;
    int i = blockIdx.x * 256 + tid;
    int v = (i < NN) ? g_deg[i] : 0;
    sm[tid] = v;
    __syncthreads();
#pragma unroll
    for (int off = 1; off < 256; off <<= 1) {
        int t = sm[tid];
        int a = (tid >= off) ? sm[tid - off] : 0;
        __syncthreads();
        sm[tid] = t + a;
        __syncthreads();
    }
    if (i < NN) g_rowptr[i] = sm[tid] - v;
    if (tid == 255) g_bsum[blockIdx.x] = sm[255];
}
__global__ void scan2_kernel() {
    __shared__ int sm[256];
    int tid = threadIdx.x;
    int v = (tid < SCAN_BLOCKS) ? g_bsum[tid] : 0;
    sm[tid] = v;
    __syncthreads();
#pragma unroll
    for (int off = 1; off < 256; off <<= 1) {
        int t = sm[tid];
        int a = (tid >= off) ? sm[tid - off] : 0;
        __syncthreads();
        sm[tid] = t + a;
        __syncthreads();
    }
    if (tid < SCAN_BLOCKS) g_bsum[tid] = sm[tid] - v;
    if (tid == 0) g_rowptr[NN] = EE;
}
__global__ void scan3_kernel() {
    int tid = threadIdx.x;
    int i = blockIdx.x * 256 + tid;
    if (i < NN) {
        int r = g_rowptr[i] + g_bsum[blockIdx.x];
        g_rowptr[i] = r;
        g_cur[i] = r;
    }
}

__global__ void scatter_kernel(const int* __restrict__ ei) {
    int e = blockIdx.x * blockDim.x + threadIdx.x;
    if (e < EE) {
        int p = atomicAdd(&g_cur[ei[EE + e]], 1);
        g_csrc[p] = ei[e];
    }
}

// ---------------- bf16 split prep ----------------
__global__ void prep_x_kernel(const float* __restrict__ x) {
    int idx = blockIdx.x * blockDim.x + threadIdx.x;   // NPAD*64 threads
    if (idx >= NPAD * 64) return;
    int row = idx >> 6, c4 = (idx & 63) << 2;
    float4 v = make_float4(0.f, 0.f, 0.f, 0.f);
    if (row < NN) v = *(const float4*)(x + (size_t)row * INC + c4);
    float vv[4] = {v.x, v.y, v.z, v.w};
    __nv_bfloat16 h[4], l[4];
#pragma unroll
    for (int i = 0; i < 4; i++) {
        h[i] = __float2bfloat16(vv[i]);
        l[i] = __float2bfloat16(vv[i] - __bfloat162float(h[i]));
    }
    size_t o = (size_t)row * KEXT + c4;
    __nv_bfloat162 t0, t1, u0, u1;
    t0.x = h[0]; t0.y = h[1]; t1.x = h[2]; t1.y = h[3];
    u0.x = l[0]; u0.y = l[1]; u1.x = l[2]; u1.y = l[3];
    *(__nv_bfloat162*)(g_xext + o)           = t0;
    *(__nv_bfloat162*)(g_xext + o + 2)       = t1;
    *(__nv_bfloat162*)(g_xext + o + 256)     = t0;
    *(__nv_bfloat162*)(g_xext + o + 258)     = t1;
    *(__nv_bfloat162*)(g_xext + o + 512)     = u0;
    *(__nv_bfloat162*)(g_xext + o + 514)     = u1;
}

__global__ void prep_B_kernel(
    const float* __restrict__ Wq, const float* __restrict__ Wk,
    const float* __restrict__ Wv, const float* __restrict__ Ws)
{
    int idx = blockIdx.x * blockDim.x + threadIdx.x;   // 256*800 threads
    if (idx >= INC * NFUSE) return;
    int kk = idx / NFUSE, n = idx % NFUSE;
    int m = n / HID, jj = n % HID;
    const float* W = (m == 0) ? Wq : (m == 1) ? Wk : (m == 2) ? Wv : Ws;
    float w = W[(size_t)kk * HID + jj];
    __nv_bfloat16 h = __float2bfloat16(w);
    __nv_bfloat16 l = __float2bfloat16(w - __bfloat162float(h));
    size_t base = (size_t)n * KEXT;
    g_Bt[base + kk]       = h;
    g_Bt[base + 256 + kk] = l;
    g_Bt[base + 512 + kk] = h;
}

// ---------------- HMMA GEMM: [Q1|K1|V1|S1](+bias) = A_ext @ B_ext^T -------------
#define GM 256
#define GN 160
#define GK 64
#define NITER (KEXT / GK)   // 12

#define ASTAGE 32768
#define BSTAGE 20480
#define NSTAGE 3
#define OFF_BIAS 0
#define OFF_A    1024
#define OFF_B    (1024 + NSTAGE * ASTAGE)
#define GSMEM_BYTES (OFF_B + NSTAGE * BSTAGE) // 160768

__device__ __forceinline__ uint32_t swz(int r, int c) {   // byte offset in a stage, c in 0..7
    return (uint32_t)(r * 128 + (((c ^ r) & 7) << 4) + ((c & ~7) << 4));
}

__global__ __launch_bounds__(512, 1) void gemm1_tc(
    const float* __restrict__ bq, const float* __restrict__ bk,
    const float* __restrict__ bv, const float* __restrict__ bs)
{
    extern __shared__ char smem[];
    const uint32_t sb = smem_u32(smem);
    const int tid  = threadIdx.x;
    const int wid  = tid >> 5;
    const int lane = tid & 31;
    const int warpm = wid & 3;
    const int warpn = wid >> 2;
    const int r0 = blockIdx.y * GM;
    const int c0 = blockIdx.x * GN;

    if (tid < GN) {
        int cg = c0 + tid;
        int m = cg / HID, jj = cg - m * HID;
        const float* bp = (m == 0) ? bq : (m == 1) ? bk : (m == 2) ? bv : bs;
        *(float*)(smem + OFF_BIAS + tid * 4) = bp[jj];
    }

    const int lr = tid >> 3, lc = tid & 7;
    const uint32_t sdA0 = swz(lr,       lc);
    const uint32_t sdA1 = swz(lr + 64,  lc);
    const uint32_t sdA2 = swz(lr + 128, lc);
    const uint32_t sdA3 = swz(lr + 192, lc);
    const uint32_t sdB0 = sdA0;
    const uint32_t sdB1 = sdA1;
    const uint32_t sdB2 = swz(lr + 128, lc);
    const __nv_bfloat16* aptr0 = g_xext + (size_t)(r0 + lr) * KEXT + lc * 8;
    const __nv_bfloat16* aptr1 = aptr0 + (size_t)64  * KEXT;
    const __nv_bfloat16* aptr2 = aptr0 + (size_t)128 * KEXT;
    const __nv_bfloat16* aptr3 = aptr0 + (size_t)192 * KEXT;
    const __nv_bfloat16* bptr0 = g_Bt + (size_t)(c0 + lr) * KEXT + lc * 8;
    const __nv_bfloat16* bptr1 = bptr0 + (size_t)64  * KEXT;
    const __nv_bfloat16* bptr2 = bptr0 + (size_t)128 * KEXT;

    auto load_stage = [&](int sidx) {
        const uint32_t Ab = sb + OFF_A + sidx * ASTAGE;
        const uint32_t Bb = sb + OFF_B + sidx * BSTAGE;
        cpasync16(Ab + sdA0, aptr0);
        cpasync16(Ab + sdA1, aptr1);
        cpasync16(Ab + sdA2, aptr2);
        cpasync16(Ab + sdA3, aptr3);
        cpasync16(Bb + sdB0, bptr0);
        cpasync16(Bb + sdB1, bptr1);
        if (tid < 256) cpasync16(Bb + sdB2, bptr2);
        CP_COMMIT();
        aptr0 += GK; aptr1 += GK; aptr2 += GK; aptr3 += GK;
        bptr0 += GK; bptr1 += GK; bptr2 += GK;
    };

    float acc[4][5][4];
#pragma unroll
    for (int mt = 0; mt < 4; mt++)
#pragma unroll
        for (int nt = 0; nt < 5; nt++)
#pragma unroll
            for (int q = 0; q < 4; q++) acc[mt][nt][q] = 0.f;

    load_stage(0);
    load_stage(1);

    const int m0 = warpm * 64;
    const int n0 = warpn * 40;
    const int lrow = lane & 15;
    const int lchunk = lane >> 4;

    for (int j = 0; j < NITER; j += NSTAGE) {
#pragma unroll
        for (int s = 0; s < NSTAGE; s++) {
            const int i = j + s;
            if (i + 1 < NITER) { CP_WAIT(1); } else { CP_WAIT(0); }
            __syncthreads();
            if (i + 2 < NITER) load_stage((s + 2) % 3);

            const uint32_t Ab = sb + OFF_A + s * ASTAGE;
            const uint32_t Bb = sb + OFF_B + s * BSTAGE;
#pragma unroll
            for (int kt = 0; kt < 4; kt++) {
                const int cbase = kt * 2 + lchunk;
                uint32_t a[4][4];
#pragma unroll
                for (int mt = 0; mt < 4; mt++)
                    ldmx4(a[mt][0], a[mt][1], a[mt][2], a[mt][3],
                          Ab + swz(m0 + mt * 16 + lrow, cbase));
                uint32_t b[5][2];
#pragma unroll
                for (int p = 0; p < 2; p++) {
                    uint32_t q0, q1, q2, q3;
                    ldmx4(q0, q1, q2, q3, Bb + swz(n0 + p * 16 + lrow, cbase));
                    b[2 * p][0] = q0; b[2 * p + 1][0] = q1;
                    b[2 * p][1] = q2; b[2 * p + 1][1] = q3;
                }
                ldmx2(b[4][0], b[4][1],
                      Bb + swz(n0 + 32 + (lane & 7), kt * 2 + ((lane >> 3) & 1)));
#pragma unroll
                for (int mt = 0; mt < 4; mt++)
#pragma unroll
                    for (int nt = 0; nt < 5; nt++)
                        mma16816(acc[mt][nt], a[mt], b[nt][0], b[nt][1]);
            }
        }
    }

    // ---- epilogue: fused bias; Q/S fp32, K/V bf16x2 into g_KV1 ----
#pragma unroll
    for (int mt = 0; mt < 4; mt++) {
#pragma unroll
        for (int h = 0; h < 2; h++) {
            int gr = r0 + m0 + mt * 16 + h * 8 + (lane >> 2);
            if (gr >= NN) continue;
#pragma unroll
            for (int nt = 0; nt < 5; nt++) {
                int jl = n0 + nt * 8 + (lane & 3) * 2;
                int cg = c0 + jl;
                int m = cg / HID, jj = cg - m * HID;
                float2 bb = *(const float2*)(smem + OFF_BIAS + jl * 4);
                float2 v;
                v.x = acc[mt][nt][2 * h]     + bb.x;
                v.y = acc[mt][nt][2 * h + 1] + bb.y;
                if (m == 0)      *(float2*)(g_Q1 + (size_t)gr * HID + jj) = v;
                else if (m == 3) *(float2*)(g_S1 + (size_t)gr * HID + jj) = v;
                else {
                    __nv_bfloat162 t;
                    t.x = __float2bfloat16(v.x);
                    t.y = __float2bfloat16(v.y);
                    int off = (m == 1) ? jj : 200 + jj;
                    *(__nv_bfloat162*)(g_KV1 + (size_t)gr * 400 + off) = t;
                }
            }
        }
    }
}

// ---------------- layer-1 edge aggregation: warp per dst, 4-edge batch ---------
__global__ __launch_bounds__(256) void edge1_kernel() {
    int warp = (blockIdx.x * blockDim.x + threadIdx.x) >> 5;
    int lane = threadIdx.x & 31;
    if (warp >= NN) return;

    const int e0 = g_rowptr[warp];
    const int e1 = g_rowptr[warp + 1];
    const float scale = 0.0707106781186547f;  // 1/sqrt(200)

    float2 q[4];
#pragma unroll
    for (int r = 0; r < 4; r++) {
        int idx = lane + 32 * r;
        if (idx < 100) {
            float2 t = ((const float2*)(g_Q1 + (size_t)warp * HID))[idx];
            q[r].x = t.x * scale; q[r].y = t.y * scale;
        } else { q[r].x = 0.f; q[r].y = 0.f; }
    }

    float2 acc[4];
#pragma unroll
    for (int r = 0; r < 4; r++) { acc[r].x = 0.f; acc[r].y = 0.f; }
    float m = __int_as_float(0xff800000);
    float s = 0.f;

    int e = e0;
    for (; e + 4 <= e1; e += 4) {
        int si[4];
#pragma unroll
        for (int t = 0; t < 4; t++) si[t] = g_csrc[e + t];
        float2 kk[4][4], vv[4][4];
#pragma unroll
        for (int t = 0; t < 4; t++) {
            const __nv_bfloat162* p = (const __nv_bfloat162*)(g_KV1 + (size_t)si[t] * 400);
#pragma unroll
            for (int r = 0; r < 4; r++) {
                int idx = lane + 32 * r;
                bool ok = (idx < 100);
                kk[t][r] = ok ? __bfloat1622float2(p[idx])       : make_float2(0.f, 0.f);
                vv[t][r] = ok ? __bfloat1622float2(p[100 + idx]) : make_float2(0.f, 0.f);
            }
        }
        float p4[4];
#pragma unroll
        for (int t = 0; t < 4; t++) {
            float d = 0.f;
#pragma unroll
            for (int r = 0; r < 4; r++) d += q[r].x * kk[t][r].x + q[r].y * kk[t][r].y;
            p4[t] = d;
        }
#pragma unroll
        for (int off = 16; off > 0; off >>= 1)
#pragma unroll
            for (int t = 0; t < 4; t++)
                p4[t] += __shfl_xor_sync(0xffffffffu, p4[t], off);

        float mx = fmaxf(fmaxf(p4[0], p4[1]), fmaxf(p4[2], p4[3]));
        float mn = fmaxf(m, mx);
        float c = __expf(m - mn);
        float w[4];
#pragma unroll
        for (int t = 0; t < 4; t++) w[t] = __expf(p4[t] - mn);
        s = s * c + w[0] + w[1] + w[2] + w[3];
#pragma unroll
        for (int r = 0; r < 4; r++) {
            float ax = acc[r].x * c, ay = acc[r].y * c;
#pragma unroll
            for (int t = 0; t < 4; t++) { ax += w[t] * vv[t][r].x; ay += w[t] * vv[t][r].y; }
            acc[r].x = ax; acc[r].y = ay;
        }
        m = mn;
    }
    for (; e < e1; e++) {
        int src = g_csrc[e];
        const __nv_bfloat162* kvp = (const __nv_bfloat162*)(g_KV1 + (size_t)src * 400);
        float2 kv[4], vv[4];
#pragma unroll
        for (int r = 0; r < 4; r++) {
            int idx = lane + 32 * r;
            bool ok = (idx < 100);
            kv[r] = ok ? __bfloat1622float2(kvp[idx])       : make_float2(0.f, 0.f);
            vv[r] = ok ? __bfloat1622float2(kvp[100 + idx]) : make_float2(0.f, 0.f);
        }
        float p = 0.f;
#pragma unroll
        for (int r = 0; r < 4; r++) p += q[r].x * kv[r].x + q[r].y * kv[r].y;
#pragma unroll
        for (int off = 16; off > 0; off >>= 1)
            p += __shfl_xor_sync(0xffffffffu, p, off);
        float mn = fmaxf(m, p);
        float c = __expf(m - mn);
        float w = __expf(p - mn);
        s = s * c + w;
#pragma unroll
        for (int r = 0; r < 4; r++) {
            acc[r].x = acc[r].x * c + w * vv[r].x;
            acc[r].y = acc[r].y * c + w * vv[r].y;
        }
        m = mn;
    }

    float inv = (e1 > e0) ? (1.f / s) : 0.f;
#pragma unroll
    for (int r = 0; r < 4; r++) {
        int idx = lane + 32 * r;
        if (idx < 100) {
            float2 sk = ((const float2*)(g_S1 + (size_t)warp * HID))[idx];
            float2 o;
            o.x = acc[r].x * inv + sk.x;
            o.y = acc[r].y * inv + sk.y;
            o.x = o.x > 0.f ? o.x : 0.f;
            o.y = o.y > 0.f ? o.y : 0.f;
            ((float2*)(g_h1 + (size_t)warp * HID))[idx] = o;
        }
    }
}

// ---------------- layer-2 projections: warp per node (coalesced) ----------------
__global__ __launch_bounds__(256) void qkv2_kernel(
    const float* __restrict__ Wq, const float* __restrict__ bq,
    const float* __restrict__ Wk, const float* __restrict__ bk,
    const float* __restrict__ Wv, const float* __restrict__ bv,
    const float* __restrict__ Ws, const float* __restrict__ bs)
{
    __shared__ float ws[8][HID];   // transposed: ws[c][k]
    __shared__ float bb[8];
    for (int l = threadIdx.x; l < HID * 8; l += blockDim.x) {
        int c = l / HID, k = l - c * HID;
        int w = c >> 1, j = c & 1;
        const float* W = (w == 0) ? Wq : (w == 1) ? Wk : (w == 2) ? Wv : Ws;
        ws[c][k] = W[k * 2 + j];
    }
    if (threadIdx.x < 8) {
        int c = threadIdx.x, w = c >> 1, j = c & 1;
        const float* B = (w == 0) ? bq : (w == 1) ? bk : (w == 2) ? bv : bs;
        bb[c] = B[j];
    }
    __syncthreads();

    int warp = blockIdx.x * 8 + (threadIdx.x >> 5);
    int lane = threadIdx.x & 31;
    if (warp >= NN) return;

    const float* h = g_h1 + (size_t)warp * HID;
    float a[8];
#pragma unroll
    for (int c = 0; c < 8; c++) a[c] = 0.f;
#pragma unroll
    for (int r = 0; r < 7; r++) {
        int d = lane + 32 * r;
        if (d < HID) {
            float hv = h[d];
#pragma unroll
            for (int c = 0; c < 8; c++) a[c] += hv * ws[c][d];
        }
    }
#pragma unroll
    for (int off = 16; off > 0; off >>= 1)
#pragma unroll
        for (int c = 0; c < 8; c++)
            a[c] += __shfl_xor_sync(0xffffffffu, a[c], off);

    if (lane == 0) {
        float4 o0, o1;
        o0.x = a[0] + bb[0]; o0.y = a[1] + bb[1]; o0.z = a[2] + bb[2]; o0.w = a[3] + bb[3];
        o1.x = a[4] + bb[4]; o1.y = a[5] + bb[5]; o1.z = a[6] + bb[6]; o1.w = a[7] + bb[7];
        *(float4*)(g_b2 + (size_t)warp * 8)     = o0;
        *(float4*)(g_b2 + (size_t)warp * 8 + 4) = o1;
    }
}

// ---------------- layer-2 edge aggregation ----------------
__global__ __launch_bounds__(256) void edge2_kernel(float* __restrict__ out) {
    int i = blockIdx.x * blockDim.x + threadIdx.x;
    if (i >= NN) return;
    const int e0 = g_rowptr[i];
    const int e1 = g_rowptr[i + 1];
    const float scale = 0.7071067811865475f;
    const float* me = g_b2 + (size_t)i * 8;
    float q0 = me[0] * scale, q1 = me[1] * scale;
    float m = __int_as_float(0xff800000);
    float s = 0.f, a0 = 0.f, a1 = 0.f;
    for (int e = e0; e < e1; e++) {
        int src = g_csrc[e];
        const float* p = g_b2 + (size_t)src * 8;
        float k0 = p[2], k1 = p[3], v0 = p[4], v1 = p[5];
        float sc = q0 * k0 + q1 * k1;
        float mn = fmaxf(m, sc);
        float c = __expf(m - mn);
        float w = __expf(sc - mn);
        s = s * c + w;
        a0 = a0 * c + w * v0;
        a1 = a1 * c + w * v1;
        m = mn;
    }
    float inv = (e1 > e0) ? (1.f / s) : 0.f;
    float o0 = a0 * inv + me[6];
    float o1 = a1 * inv + me[7];
    out[(size_t)i * 2 + 0] = o0 > 0.f ? o0 : 0.f;
    out[(size_t)i * 2 + 1] = o1 > 0.f ? o1 : 0.f;
}

// ---------------- launch: forked graph (CSR chain || prep+gemm) ----------------
extern "C" void kernel_launch(void* const* d_in, const int* in_sizes, int n_in,
                              void* d_out, int out_size) {
    const float* x   = (const float*)d_in[0];
    const int*   ei  = (const int*)d_in[1];
    const float *Wq1 = (const float*)d_in[2],  *bq1 = (const float*)d_in[3];
    const float *Wk1 = (const float*)d_in[4],  *bk1 = (const float*)d_in[5];
    const float *Wv1 = (const float*)d_in[6],  *bv1 = (const float*)d_in[7];
    const float *Ws1 = (const float*)d_in[8],  *bs1 = (const float*)d_in[9];
    const float *Wq2 = (const float*)d_in[10], *bq2 = (const float*)d_in[11];
    const float *Wk2 = (const float*)d_in[12], *bk2 = (const float*)d_in[13];
    const float *Wv2 = (const float*)d_in[14], *bv2 = (const float*)d_in[15];
    const float *Ws2 = (const float*)d_in[16], *bs2 = (const float*)d_in[17];
    float* out = (float*)d_out;

    // one-time creation (first, uncaptured correctness call); reused thereafter
    static cudaStream_t s2 = nullptr;
    static cudaEvent_t evFork = nullptr, evJoin = nullptr;
    if (s2 == nullptr) {
        cudaStreamCreateWithFlags(&s2, cudaStreamNonBlocking);
        cudaEventCreateWithFlags(&evFork, cudaEventDisableTiming);
        cudaEventCreateWithFlags(&evJoin, cudaEventDisableTiming);
        cudaFuncSetAttribute(gemm1_tc, cudaFuncAttributeMaxDynamicSharedMemorySize, GSMEM_BYTES);
    }

    // fork: branch B (CSR build) on s2, independent of branch A
    cudaEventRecord(evFork, 0);
    cudaStreamWaitEvent(s2, evFork, 0);

    zero_deg_kernel<<<(NN + 255) / 256, 256, 0, s2>>>();
    count_kernel<<<(EE + 255) / 256, 256, 0, s2>>>(ei);
    scan1_kernel<<<SCAN_BLOCKS, 256, 0, s2>>>();
    scan2_kernel<<<1, 256, 0, s2>>>();
    scan3_kernel<<<SCAN_BLOCKS, 256, 0, s2>>>();
    scatter_kernel<<<(EE + 255) / 256, 256, 0, s2>>>(ei);
    cudaEventRecord(evJoin, s2);

    // branch A: prep + gemm on default stream
    prep_x_kernel<<<(NPAD * 64 + 255) / 256, 256>>>(x);
    prep_B_kernel<<<(INC * NFUSE + 255) / 256, 256>>>(Wq1, Wk1, Wv1, Ws1);
    dim3 g1(NFUSE / GN, NPAD / GM);   // (5, 196)
    gemm1_tc<<<g1, 512, GSMEM_BYTES>>>(bq1, bk1, bv1, bs1);

    // join: edge1 needs both gemm (stream order) and CSR (event)
    cudaStreamWaitEvent(0, evJoin, 0);

    edge1_kernel<<<(NN * 32 + 255) / 256, 256>>>();
    qkv2_kernel<<<(NN * 32 + 255) / 256, 256>>>(Wq2, bq2, Wk2, bk2, Wv2, bv2, Ws2, bs2);
    edge2_kernel<<<(NN + 255) / 256, 256>>>(out);
}

// round 16
// speedup vs baseline: 1.2467x; 1.0242x over previous
#include <cuda_runtime.h>
#include <cuda_bf16.h>
#include <cstdint>

#define NN 50000
#define EE 800000
#define INC 256
#define HID 200
#define NPAD 50176              // 196 * 256
#define NFUSE 800               // 4 * HID
#define KEXT 768                // A_ext = [x_hi | x_hi | x_lo], B_ext = [W_hi; W_lo; W_hi]
#define SCAN_BLOCKS 196         // 196 * 256 = 50176 >= NN

// ---------------- scratch (static device globals; no allocations) ----------------
__device__ float g_Q1[NN * HID];
__device__ __nv_bfloat16 g_KV1[(size_t)NN * 400];   // [node][K(200) | V(200)] bf16
__device__ float g_S1[NN * HID];
__device__ float g_b2[NN * 8];
__device__ int   g_deg[NN];
__device__ int   g_cur[NN];
__device__ int   g_rowptr[NN + 1];
__device__ int   g_csrc[EE];
__device__ int   g_bsum[SCAN_BLOCKS];
__device__ __nv_bfloat16 g_xext[(size_t)NPAD * KEXT];   // [row][hi(256)|hi(256)|lo(256)]
__device__ __nv_bfloat16 g_Bt[(size_t)NFUSE * KEXT];

// ---------------- PTX helpers (compute_100-safe) ----------------
__device__ __forceinline__ uint32_t smem_u32(const void* p) {
    uint32_t a;
    asm("{ .reg .u64 t; cvta.to.shared.u64 t, %1; cvt.u32.u64 %0, t; }" : "=r"(a) : "l"(p));
    return a;
}
__device__ __forceinline__ void cpasync16(uint32_t dst, const void* src) {
    asm volatile("cp.async.cg.shared.global [%0], [%1], 16;" :: "r"(dst), "l"(src));
}
#define CP_COMMIT() asm volatile("cp.async.commit_group;" ::: "memory")
#define CP_WAIT(n)  asm volatile("cp.async.wait_group %0;" :: "n"(n) : "memory")

__device__ __forceinline__ void ldmx4(uint32_t& r0, uint32_t& r1, uint32_t& r2, uint32_t& r3,
                                      uint32_t addr) {
    asm volatile("ldmatrix.sync.aligned.m8n8.x4.shared.b16 {%0,%1,%2,%3}, [%4];"
                 : "=r"(r0), "=r"(r1), "=r"(r2), "=r"(r3) : "r"(addr));
}
__device__ __forceinline__ void ldmx2(uint32_t& r0, uint32_t& r1, uint32_t addr) {
    asm volatile("ldmatrix.sync.aligned.m8n8.x2.shared.b16 {%0,%1}, [%2];"
                 : "=r"(r0), "=r"(r1) : "r"(addr));
}
__device__ __forceinline__ void mma16816(float* d, const uint32_t* a, uint32_t b0, uint32_t b1) {
    asm volatile(
        "mma.sync.aligned.m16n8k16.row.col.f32.bf16.bf16.f32 "
        "{%0,%1,%2,%3}, {%4,%5,%6,%7}, {%8,%9}, {%0,%1,%2,%3};"
        : "+f"(d[0]), "+f"(d[1]), "+f"(d[2]), "+f"(d[3])
        : "r"(a[0]), "r"(a[1]), "r"(a[2]), "r"(a[3]), "r"(b0), "r"(b1));
}

// ---------------- CSR build ----------------
__global__ void zero_deg_kernel() {
    int i = blockIdx.x * blockDim.x + threadIdx.x;
    if (i < NN) g_deg[i] = 0;
}
__global__ void count_kernel(const int* __restrict__ ei) {
    int e = blockIdx.x * blockDim.x + threadIdx.x;
    if (e < EE) atomicAdd(&g_deg[ei[EE + e]], 1);
}

__global__ void scan1_kernel() {
    __shared__ int sm[256];
    int tid = threadIdx.x;
    int i = blockIdx.x * 256 + tid;
    int v = (i < NN) ? g_deg[i] : 0;
    sm[tid] = v;
    __syncthreads();
#pragma unroll
    for (int off = 1; off < 256; off <<= 1) {
        int t = sm[tid];
        int a = (tid >= off) ? sm[tid - off] : 0;
        __syncthreads();
        sm[tid] = t + a;
        __syncthreads();
    }
    if (i < NN) g_rowptr[i] = sm[tid] - v;
    if (tid == 255) g_bsum[blockIdx.x] = sm[255];
}
__global__ void scan2_kernel() {
    __shared__ int sm[256];
    int tid = threadIdx.x;
    int v = (tid < SCAN_BLOCKS) ? g_bsum[tid] : 0;
    sm[tid] = v;
    __syncthreads();
#pragma unroll
    for (int off = 1; off < 256; off <<= 1) {
        int t = sm[tid];
        int a = (tid >= off) ? sm[tid - off] : 0;
        __syncthreads();
        sm[tid] = t + a;
        __syncthreads();
    }
    if (tid < SCAN_BLOCKS) g_bsum[tid] = sm[tid] - v;
    if (tid == 0) g_rowptr[NN] = EE;
}
__global__ void scan3_kernel() {
    int tid = threadIdx.x;
    int i = blockIdx.x * 256 + tid;
    if (i < NN) {
        int r = g_rowptr[i] + g_bsum[blockIdx.x];
        g_rowptr[i] = r;
        g_cur[i] = r;
    }
}

__global__ void scatter_kernel(const int* __restrict__ ei) {
    int e = blockIdx.x * blockDim.x + threadIdx.x;
    if (e < EE) {
        int p = atomicAdd(&g_cur[ei[EE + e]], 1);
        g_csrc[p] = ei[e];
    }
}

// ---------------- bf16 split prep ----------------
__global__ void prep_x_kernel(const float* __restrict__ x) {
    int idx = blockIdx.x * blockDim.x + threadIdx.x;   // NPAD*64 threads
    if (idx >= NPAD * 64) return;
    int row = idx >> 6, c4 = (idx & 63) << 2;
    float4 v = make_float4(0.f, 0.f, 0.f, 0.f);
    if (row < NN) v = *(const float4*)(x + (size_t)row * INC + c4);
    float vv[4] = {v.x, v.y, v.z, v.w};
    __nv_bfloat16 h[4], l[4];
#pragma unroll
    for (int i = 0; i < 4; i++) {
        h[i] = __float2bfloat16(vv[i]);
        l[i] = __float2bfloat16(vv[i] - __bfloat162float(h[i]));
    }
    size_t o = (size_t)row * KEXT + c4;
    __nv_bfloat162 t0, t1, u0, u1;
    t0.x = h[0]; t0.y = h[1]; t1.x = h[2]; t1.y = h[3];
    u0.x = l[0]; u0.y = l[1]; u1.x = l[2]; u1.y = l[3];
    *(__nv_bfloat162*)(g_xext + o)           = t0;
    *(__nv_bfloat162*)(g_xext + o + 2)       = t1;
    *(__nv_bfloat162*)(g_xext + o + 256)     = t0;
    *(__nv_bfloat162*)(g_xext + o + 258)     = t1;
    *(__nv_bfloat162*)(g_xext + o + 512)     = u0;
    *(__nv_bfloat162*)(g_xext + o + 514)     = u1;
}

__global__ void prep_B_kernel(
    const float* __restrict__ Wq, const float* __restrict__ Wk,
    const float* __restrict__ Wv, const float* __restrict__ Ws)
{
    int idx = blockIdx.x * blockDim.x + threadIdx.x;   // 256*800 threads
    if (idx >= INC * NFUSE) return;
    int kk = idx / NFUSE, n = idx % NFUSE;
    int m = n / HID, jj = n % HID;
    const float* W = (m == 0) ? Wq : (m == 1) ? Wk : (m == 2) ? Wv : Ws;
    float w = W[(size_t)kk * HID + jj];
    __nv_bfloat16 h = __float2bfloat16(w);
    __nv_bfloat16 l = __float2bfloat16(w - __bfloat162float(h));
    size_t base = (size_t)n * KEXT;
    g_Bt[base + kk]       = h;
    g_Bt[base + 256 + kk] = l;
    g_Bt[base + 512 + kk] = h;
}

// ---------------- HMMA GEMM: [Q1|K1|V1|S1](+bias) = A_ext @ B_ext^T -------------
#define GM 256
#define GN 160
#define GK 64
#define NITER (KEXT / GK)   // 12

#define ASTAGE 32768
#define BSTAGE 20480
#define NSTAGE 3
#define OFF_BIAS 0
#define OFF_A    1024
#define OFF_B    (1024 + NSTAGE * ASTAGE)
#define GSMEM_BYTES (OFF_B + NSTAGE * BSTAGE) // 160768

__device__ __forceinline__ uint32_t swz(int r, int c) {   // byte offset in a stage, c in 0..7
    return (uint32_t)(r * 128 + (((c ^ r) & 7) << 4) + ((c & ~7) << 4));
}

__global__ __launch_bounds__(512, 1) void gemm1_tc(
    const float* __restrict__ bq, const float* __restrict__ bk,
    const float* __restrict__ bv, const float* __restrict__ bs)
{
    extern __shared__ char smem[];
    const uint32_t sb = smem_u32(smem);
    const int tid  = threadIdx.x;
    const int wid  = tid >> 5;
    const int lane = tid & 31;
    const int warpm = wid & 3;
    const int warpn = wid >> 2;
    const int r0 = blockIdx.y * GM;
    const int c0 = blockIdx.x * GN;

    if (tid < GN) {
        int cg = c0 + tid;
        int m = cg / HID, jj = cg - m * HID;
        const float* bp = (m == 0) ? bq : (m == 1) ? bk : (m == 2) ? bv : bs;
        *(float*)(smem + OFF_BIAS + tid * 4) = bp[jj];
    }

    const int lr = tid >> 3, lc = tid & 7;
    const uint32_t sdA0 = swz(lr,       lc);
    const uint32_t sdA1 = swz(lr + 64,  lc);
    const uint32_t sdA2 = swz(lr + 128, lc);
    const uint32_t sdA3 = swz(lr + 192, lc);
    const uint32_t sdB0 = sdA0;
    const uint32_t sdB1 = sdA1;
    const uint32_t sdB2 = swz(lr + 128, lc);
    const __nv_bfloat16* aptr0 = g_xext + (size_t)(r0 + lr) * KEXT + lc * 8;
    const __nv_bfloat16* aptr1 = aptr0 + (size_t)64  * KEXT;
    const __nv_bfloat16* aptr2 = aptr0 + (size_t)128 * KEXT;
    const __nv_bfloat16* aptr3 = aptr0 + (size_t)192 * KEXT;
    const __nv_bfloat16* bptr0 = g_Bt + (size_t)(c0 + lr) * KEXT + lc * 8;
    const __nv_bfloat16* bptr1 = bptr0 + (size_t)64  * KEXT;
    const __nv_bfloat16* bptr2 = bptr0 + (size_t)128 * KEXT;

    auto load_stage = [&](int sidx) {
        const uint32_t Ab = sb + OFF_A + sidx * ASTAGE;
        const uint32_t Bb = sb + OFF_B + sidx * BSTAGE;
        cpasync16(Ab + sdA0, aptr0);
        cpasync16(Ab + sdA1, aptr1);
        cpasync16(Ab + sdA2, aptr2);
        cpasync16(Ab + sdA3, aptr3);
        cpasync16(Bb + sdB0, bptr0);
        cpasync16(Bb + sdB1, bptr1);
        if (tid < 256) cpasync16(Bb + sdB2, bptr2);
        CP_COMMIT();
        aptr0 += GK; aptr1 += GK; aptr2 += GK; aptr3 += GK;
        bptr0 += GK; bptr1 += GK; bptr2 += GK;
    };

    float acc[4][5][4];
#pragma unroll
    for (int mt = 0; mt < 4; mt++)
#pragma unroll
        for (int nt = 0; nt < 5; nt++)
#pragma unroll
            for (int q = 0; q < 4; q++) acc[mt][nt][q] = 0.f;

    load_stage(0);
    load_stage(1);

    const int m0 = warpm * 64;
    const int n0 = warpn * 40;
    const int lrow = lane & 15;
    const int lchunk = lane >> 4;

    for (int j = 0; j < NITER; j += NSTAGE) {
#pragma unroll
        for (int s = 0; s < NSTAGE; s++) {
            const int i = j + s;
            if (i + 1 < NITER) { CP_WAIT(1); } else { CP_WAIT(0); }
            __syncthreads();
            if (i + 2 < NITER) load_stage((s + 2) % 3);

            const uint32_t Ab = sb + OFF_A + s * ASTAGE;
            const uint32_t Bb = sb + OFF_B + s * BSTAGE;
#pragma unroll
            for (int kt = 0; kt < 4; kt++) {
                const int cbase = kt * 2 + lchunk;
                uint32_t a[4][4];
#pragma unroll
                for (int mt = 0; mt < 4; mt++)
                    ldmx4(a[mt][0], a[mt][1], a[mt][2], a[mt][3],
                          Ab + swz(m0 + mt * 16 + lrow, cbase));
                uint32_t b[5][2];
#pragma unroll
                for (int p = 0; p < 2; p++) {
                    uint32_t q0, q1, q2, q3;
                    ldmx4(q0, q1, q2, q3, Bb + swz(n0 + p * 16 + lrow, cbase));
                    b[2 * p][0] = q0; b[2 * p + 1][0] = q1;
                    b[2 * p][1] = q2; b[2 * p + 1][1] = q3;
                }
                ldmx2(b[4][0], b[4][1],
                      Bb + swz(n0 + 32 + (lane & 7), kt * 2 + ((lane >> 3) & 1)));
#pragma unroll
                for (int mt = 0; mt < 4; mt++)
#pragma unroll
                    for (int nt = 0; nt < 5; nt++)
                        mma16816(acc[mt][nt], a[mt], b[nt][0], b[nt][1]);
            }
        }
    }

    // ---- epilogue: fused bias; Q/S fp32, K/V bf16x2 into g_KV1 ----
#pragma unroll
    for (int mt = 0; mt < 4; mt++) {
#pragma unroll
        for (int h = 0; h < 2; h++) {
            int gr = r0 + m0 + mt * 16 + h * 8 + (lane >> 2);
            if (gr >= NN) continue;
#pragma unroll
            for (int nt = 0; nt < 5; nt++) {
                int jl = n0 + nt * 8 + (lane & 3) * 2;
                int cg = c0 + jl;
                int m = cg / HID, jj = cg - m * HID;
                float2 bb = *(const float2*)(smem + OFF_BIAS + jl * 4);
                float2 v;
                v.x = acc[mt][nt][2 * h]     + bb.x;
                v.y = acc[mt][nt][2 * h + 1] + bb.y;
                if (m == 0)      *(float2*)(g_Q1 + (size_t)gr * HID + jj) = v;
                else if (m == 3) *(float2*)(g_S1 + (size_t)gr * HID + jj) = v;
                else {
                    __nv_bfloat162 t;
                    t.x = __float2bfloat16(v.x);
                    t.y = __float2bfloat16(v.y);
                    int off = (m == 1) ? jj : 200 + jj;
                    *(__nv_bfloat162*)(g_KV1 + (size_t)gr * 400 + off) = t;
                }
            }
        }
    }
}

// ------- layer-1 edge aggregation + fused layer-2 projection (warp per dst) ----
__global__ __launch_bounds__(256) void edge1_kernel(
    const float* __restrict__ Wq, const float* __restrict__ bq,
    const float* __restrict__ Wk, const float* __restrict__ bk,
    const float* __restrict__ Wv, const float* __restrict__ bv,
    const float* __restrict__ Ws, const float* __restrict__ bs)
{
    __shared__ float ws[8][HID];   // transposed W2: ws[c][k]
    __shared__ float bb2[8];
    for (int l = threadIdx.x; l < HID * 8; l += blockDim.x) {
        int c = l / HID, k = l - c * HID;
        int w = c >> 1, j = c & 1;
        const float* W = (w == 0) ? Wq : (w == 1) ? Wk : (w == 2) ? Wv : Ws;
        ws[c][k] = W[k * 2 + j];
    }
    if (threadIdx.x < 8) {
        int c = threadIdx.x, w = c >> 1, j = c & 1;
        const float* B = (w == 0) ? bq : (w == 1) ? bk : (w == 2) ? bv : bs;
        bb2[c] = B[j];
    }
    __syncthreads();

    int warp = blockIdx.x * 8 + (threadIdx.x >> 5);
    int lane = threadIdx.x & 31;
    if (warp >= NN) return;

    const int e0 = g_rowptr[warp];
    const int e1 = g_rowptr[warp + 1];
    const float scale = 0.0707106781186547f;  // 1/sqrt(200)

    float2 q[4];
#pragma unroll
    for (int r = 0; r < 4; r++) {
        int idx = lane + 32 * r;
        if (idx < 100) {
            float2 t = ((const float2*)(g_Q1 + (size_t)warp * HID))[idx];
            q[r].x = t.x * scale; q[r].y = t.y * scale;
        } else { q[r].x = 0.f; q[r].y = 0.f; }
    }

    float2 acc[4];
#pragma unroll
    for (int r = 0; r < 4; r++) { acc[r].x = 0.f; acc[r].y = 0.f; }
    float m = __int_as_float(0xff800000);
    float s = 0.f;

    int e = e0;
    for (; e + 4 <= e1; e += 4) {
        int si[4];
#pragma unroll
        for (int t = 0; t < 4; t++) si[t] = g_csrc[e + t];
        float2 kk[4][4], vv[4][4];
#pragma unroll
        for (int t = 0; t < 4; t++) {
            const __nv_bfloat162* p = (const __nv_bfloat162*)(g_KV1 + (size_t)si[t] * 400);
#pragma unroll
            for (int r = 0; r < 4; r++) {
                int idx = lane + 32 * r;
                bool ok = (idx < 100);
                kk[t][r] = ok ? __bfloat1622float2(p[idx])       : make_float2(0.f, 0.f);
                vv[t][r] = ok ? __bfloat1622float2(p[100 + idx]) : make_float2(0.f, 0.f);
            }
        }
        float p4[4];
#pragma unroll
        for (int t = 0; t < 4; t++) {
            float d = 0.f;
#pragma unroll
            for (int r = 0; r < 4; r++) d += q[r].x * kk[t][r].x + q[r].y * kk[t][r].y;
            p4[t] = d;
        }
#pragma unroll
        for (int off = 16; off > 0; off >>= 1)
#pragma unroll
            for (int t = 0; t < 4; t++)
                p4[t] += __shfl_xor_sync(0xffffffffu, p4[t], off);

        float mx = fmaxf(fmaxf(p4[0], p4[1]), fmaxf(p4[2], p4[3]));
        float mn = fmaxf(m, mx);
        float c = __expf(m - mn);
        float w[4];
#pragma unroll
        for (int t = 0; t < 4; t++) w[t] = __expf(p4[t] - mn);
        s = s * c + w[0] + w[1] + w[2] + w[3];
#pragma unroll
        for (int r = 0; r < 4; r++) {
            float ax = acc[r].x * c, ay = acc[r].y * c;
#pragma unroll
            for (int t = 0; t < 4; t++) { ax += w[t] * vv[t][r].x; ay += w[t] * vv[t][r].y; }
            acc[r].x = ax; acc[r].y = ay;
        }
        m = mn;
    }
    for (; e < e1; e++) {
        int src = g_csrc[e];
        const __nv_bfloat162* kvp = (const __nv_bfloat162*)(g_KV1 + (size_t)src * 400);
        float2 kv[4], vv[4];
#pragma unroll
        for (int r = 0; r < 4; r++) {
            int idx = lane + 32 * r;
            bool ok = (idx < 100);
            kv[r] = ok ? __bfloat1622float2(kvp[idx])       : make_float2(0.f, 0.f);
            vv[r] = ok ? __bfloat1622float2(kvp[100 + idx]) : make_float2(0.f, 0.f);
        }
        float p = 0.f;
#pragma unroll
        for (int r = 0; r < 4; r++) p += q[r].x * kv[r].x + q[r].y * kv[r].y;
#pragma unroll
        for (int off = 16; off > 0; off >>= 1)
            p += __shfl_xor_sync(0xffffffffu, p, off);
        float mn = fmaxf(m, p);
        float c = __expf(m - mn);
        float w = __expf(p - mn);
        s = s * c + w;
#pragma unroll
        for (int r = 0; r < 4; r++) {
            acc[r].x = acc[r].x * c + w * vv[r].x;
            acc[r].y = acc[r].y * c + w * vv[r].y;
        }
        m = mn;
    }

    // ---- epilogue: h = relu(agg/s + skip) in registers, then project to 8 outs --
    float inv = (e1 > e0) ? (1.f / s) : 0.f;
    float a2[8];
#pragma unroll
    for (int c = 0; c < 8; c++) a2[c] = 0.f;
#pragma unroll
    for (int r = 0; r < 4; r++) {
        int idx = lane + 32 * r;
        if (idx < 100) {
            float2 sk = ((const float2*)(g_S1 + (size_t)warp * HID))[idx];
            float hx = acc[r].x * inv + sk.x;
            float hy = acc[r].y * inv + sk.y;
            hx = hx > 0.f ? hx : 0.f;
            hy = hy > 0.f ? hy : 0.f;
            int d0 = idx * 2;
#pragma unroll
            for (int c = 0; c < 8; c++)
                a2[c] += hx * ws[c][d0] + hy * ws[c][d0 + 1];
        }
    }
#pragma unroll
    for (int off = 16; off > 0; off >>= 1)
#pragma unroll
        for (int c = 0; c < 8; c++)
            a2[c] += __shfl_xor_sync(0xffffffffu, a2[c], off);

    if (lane == 0) {
        float4 o0, o1;
        o0.x = a2[0] + bb2[0]; o0.y = a2[1] + bb2[1]; o0.z = a2[2] + bb2[2]; o0.w = a2[3] + bb2[3];
        o1.x = a2[4] + bb2[4]; o1.y = a2[5] + bb2[5]; o1.z = a2[6] + bb2[6]; o1.w = a2[7] + bb2[7];
        *(float4*)(g_b2 + (size_t)warp * 8)     = o0;
        *(float4*)(g_b2 + (size_t)warp * 8 + 4) = o1;
    }
}

// ---------------- layer-2 edge aggregation ----------------
__global__ __launch_bounds__(256) void edge2_kernel(float* __restrict__ out) {
    int i = blockIdx.x * blockDim.x + threadIdx.x;
    if (i >= NN) return;
    const int e0 = g_rowptr[i];
    const int e1 = g_rowptr[i + 1];
    const float scale = 0.7071067811865475f;
    const float* me = g_b2 + (size_t)i * 8;
    float q0 = me[0] * scale, q1 = me[1] * scale;
    float m = __int_as_float(0xff800000);
    float s = 0.f, a0 = 0.f, a1 = 0.f;
    for (int e = e0; e < e1; e++) {
        int src = g_csrc[e];
        const float* p = g_b2 + (size_t)src * 8;
        float k0 = p[2], k1 = p[3], v0 = p[4], v1 = p[5];
        float sc = q0 * k0 + q1 * k1;
        float mn = fmaxf(m, sc);
        float c = __expf(m - mn);
        float w = __expf(sc - mn);
        s = s * c + w;
        a0 = a0 * c + w * v0;
        a1 = a1 * c + w * v1;
        m = mn;
    }
    float inv = (e1 > e0) ? (1.f / s) : 0.f;
    float o0 = a0 * inv + me[6];
    float o1 = a1 * inv + me[7];
    out[(size_t)i * 2 + 0] = o0 > 0.f ? o0 : 0.f;
    out[(size_t)i * 2 + 1] = o1 > 0.f ? o1 : 0.f;
}

// ---------------- launch: forked graph (prep_B + CSR chain || prep_x + gemm) ---
extern "C" void kernel_launch(void* const* d_in, const int* in_sizes, int n_in,
                              void* d_out, int out_size) {
    const float* x   = (const float*)d_in[0];
    const int*   ei  = (const int*)d_in[1];
    const float *Wq1 = (const float*)d_in[2],  *bq1 = (const float*)d_in[3];
    const float *Wk1 = (const float*)d_in[4],  *bk1 = (const float*)d_in[5];
    const float *Wv1 = (const float*)d_in[6],  *bv1 = (const float*)d_in[7];
    const float *Ws1 = (const float*)d_in[8],  *bs1 = (const float*)d_in[9];
    const float *Wq2 = (const float*)d_in[10], *bq2 = (const float*)d_in[11];
    const float *Wk2 = (const float*)d_in[12], *bk2 = (const float*)d_in[13];
    const float *Wv2 = (const float*)d_in[14], *bv2 = (const float*)d_in[15];
    const float *Ws2 = (const float*)d_in[16], *bs2 = (const float*)d_in[17];
    float* out = (float*)d_out;

    // one-time creation (first, uncaptured correctness call); reused thereafter
    static cudaStream_t s2 = nullptr;
    static cudaEvent_t evFork = nullptr, evJoin = nullptr, evB = nullptr;
    if (s2 == nullptr) {
        cudaStreamCreateWithFlags(&s2, cudaStreamNonBlocking);
        cudaEventCreateWithFlags(&evFork, cudaEventDisableTiming);
        cudaEventCreateWithFlags(&evJoin, cudaEventDisableTiming);
        cudaEventCreateWithFlags(&evB, cudaEventDisableTiming);
        cudaFuncSetAttribute(gemm1_tc, cudaFuncAttributeMaxDynamicSharedMemorySize, GSMEM_BYTES);
    }

    // fork: branch B (prep_B + CSR build) on s2
    cudaEventRecord(evFork, 0);
    cudaStreamWaitEvent(s2, evFork, 0);

    prep_B_kernel<<<(INC * NFUSE + 255) / 256, 256, 0, s2>>>(Wq1, Wk1, Wv1, Ws1);
    cudaEventRecord(evB, s2);                 // gemm needs g_Bt
    zero_deg_kernel<<<(NN + 255) / 256, 256, 0, s2>>>();
    count_kernel<<<(EE + 255) / 256, 256, 0, s2>>>(ei);
    scan1_kernel<<<SCAN_BLOCKS, 256, 0, s2>>>();
    scan2_kernel<<<1, 256, 0, s2>>>();
    scan3_kernel<<<SCAN_BLOCKS, 256, 0, s2>>>();
    scatter_kernel<<<(EE + 255) / 256, 256, 0, s2>>>(ei);
    cudaEventRecord(evJoin, s2);

    // branch A: prep_x + gemm on default stream
    prep_x_kernel<<<(NPAD * 64 + 255) / 256, 256>>>(x);
    cudaStreamWaitEvent(0, evB, 0);           // wait for g_Bt
    dim3 g1(NFUSE / GN, NPAD / GM);   // (5, 196)
    gemm1_tc<<<g1, 512, GSMEM_BYTES>>>(bq1, bk1, bv1, bs1);

    // join: edge1 needs both gemm (stream order) and CSR (event)
    cudaStreamWaitEvent(0, evJoin, 0);

    edge1_kernel<<<(NN * 32 + 255) / 256, 256>>>(Wq2, bq2, Wk2, bk2, Wv2, bv2, Ws2, bs2);
    edge2_kernel<<<(NN + 255) / 256, 256>>>(out);
}

// round 17
// speedup vs baseline: 1.3158x; 1.0554x over previous
#include <cuda_runtime.h>
#include <cuda_bf16.h>
#include <cstdint>

#define NN 50000
#define EE 800000
#define INC 256
#define HID 200
#define NPAD 50176              // 196 * 256
#define NFUSE 800               // 4 * HID
#define KEXT 768                // B_ext = [W_hi; W_lo; W_hi]; A segs: hi,hi,lo
#define XCOLS 512               // g_xext = [hi(256) | lo(256)]
#define SCAN_BLOCKS 196

// ---------------- scratch (static device globals; no allocations) ----------------
__device__ __nv_bfloat16 g_Q1[NN * HID];            // pre-scaled by 1/sqrt(200), bf16
__device__ __nv_bfloat16 g_KV1[(size_t)NN * 400];   // [node][K(200) | V(200)] bf16
__device__ float g_S1[NN * HID];
__device__ float g_b2[NN * 8];
__device__ int   g_deg[NN];
__device__ int   g_cur[NN];
__device__ int   g_rowptr[NN + 1];
__device__ int   g_csrc[EE];
__device__ int   g_bsum[SCAN_BLOCKS];
__device__ __nv_bfloat16 g_xext[(size_t)NPAD * XCOLS];
__device__ __nv_bfloat16 g_Bt[(size_t)NFUSE * KEXT];

// ---------------- PTX helpers (compute_100-safe) ----------------
__device__ __forceinline__ uint32_t smem_u32(const void* p) {
    uint32_t a;
    asm("{ .reg .u64 t; cvta.to.shared.u64 t, %1; cvt.u32.u64 %0, t; }" : "=r"(a) : "l"(p));
    return a;
}
__device__ __forceinline__ void cpasync16(uint32_t dst, const void* src) {
    asm volatile("cp.async.cg.shared.global [%0], [%1], 16;" :: "r"(dst), "l"(src));
}
#define CP_COMMIT() asm volatile("cp.async.commit_group;" ::: "memory")
#define CP_WAIT(n)  asm volatile("cp.async.wait_group %0;" :: "n"(n) : "memory")

__device__ __forceinline__ void ldmx4(uint32_t& r0, uint32_t& r1, uint32_t& r2, uint32_t& r3,
                                      uint32_t addr) {
    asm volatile("ldmatrix.sync.aligned.m8n8.x4.shared.b16 {%0,%1,%2,%3}, [%4];"
                 : "=r"(r0), "=r"(r1), "=r"(r2), "=r"(r3) : "r"(addr));
}
__device__ __forceinline__ void ldmx2(uint32_t& r0, uint32_t& r1, uint32_t addr) {
    asm volatile("ldmatrix.sync.aligned.m8n8.x2.shared.b16 {%0,%1}, [%2];"
                 : "=r"(r0), "=r"(r1) : "r"(addr));
}
__device__ __forceinline__ void mma16816(float* d, const uint32_t* a, uint32_t b0, uint32_t b1) {
    asm volatile(
        "mma.sync.aligned.m16n8k16.row.col.f32.bf16.bf16.f32 "
        "{%0,%1,%2,%3}, {%4,%5,%6,%7}, {%8,%9}, {%0,%1,%2,%3};"
        : "+f"(d[0]), "+f"(d[1]), "+f"(d[2]), "+f"(d[3])
        : "r"(a[0]), "r"(a[1]), "r"(a[2]), "r"(a[3]), "r"(b0), "r"(b1));
}

// ---------------- CSR build ----------------
__global__ void zero_deg_kernel() {
    int i = blockIdx.x * blockDim.x + threadIdx.x;
    if (i < NN) g_deg[i] = 0;
}
__global__ void count_kernel(const int* __restrict__ ei) {
    int e = blockIdx.x * blockDim.x + threadIdx.x;
    if (e < EE) atomicAdd(&g_deg[ei[EE + e]], 1);
}

__global__ void scan1_kernel() {
    __shared__ int sm[256];
    int tid = threadIdx.x;
    int i = blockIdx.x * 256 + tid;
    int v = (i < NN) ? g_deg[i] : 0;
    sm[tid] = v;
    __syncthreads();
#pragma unroll
    for (int off = 1; off < 256; off <<= 1) {
        int t = sm[tid];
        int a = (tid >= off) ? sm[tid - off] : 0;
        __syncthreads();
        sm[tid] = t + a;
        __syncthreads();
    }
    if (i < NN) g_rowptr[i] = sm[tid] - v;
    if (tid == 255) g_bsum[blockIdx.x] = sm[255];
}
__global__ void scan2_kernel() {
    __shared__ int sm[256];
    int tid = threadIdx.x;
    int v = (tid < SCAN_BLOCKS) ? g_bsum[tid] : 0;
    sm[tid] = v;
    __syncthreads();
#pragma unroll
    for (int off = 1; off < 256; off <<= 1) {
        int t = sm[tid];
        int a = (tid >= off) ? sm[tid - off] : 0;
        __syncthreads();
        sm[tid] = t + a;
        __syncthreads();
    }
    if (tid < SCAN_BLOCKS) g_bsum[tid] = sm[tid] - v;
    if (tid == 0) g_rowptr[NN] = EE;
}
__global__ void scan3_kernel() {
    int tid = threadIdx.x;
    int i = blockIdx.x * 256 + tid;
    if (i < NN) {
        int r = g_rowptr[i] + g_bsum[blockIdx.x];
        g_rowptr[i] = r;
        g_cur[i] = r;
    }
}

__global__ void scatter_kernel(const int* __restrict__ ei) {
    int e = blockIdx.x * blockDim.x + threadIdx.x;
    if (e < EE) {
        int p = atomicAdd(&g_cur[ei[EE + e]], 1);
        g_csrc[p] = ei[e];
    }
}

// ---------------- bf16 split prep ----------------
__global__ void prep_x_kernel(const float* __restrict__ x) {
    int idx = blockIdx.x * blockDim.x + threadIdx.x;   // NPAD*64 threads
    if (idx >= NPAD * 64) return;
    int row = idx >> 6, c4 = (idx & 63) << 2;
    float4 v = make_float4(0.f, 0.f, 0.f, 0.f);
    if (row < NN) v = *(const float4*)(x + (size_t)row * INC + c4);
    float vv[4] = {v.x, v.y, v.z, v.w};
    __nv_bfloat16 h[4], l[4];
#pragma unroll
    for (int i = 0; i < 4; i++) {
        h[i] = __float2bfloat16(vv[i]);
        l[i] = __float2bfloat16(vv[i] - __bfloat162float(h[i]));
    }
    size_t o = (size_t)row * XCOLS + c4;
    __nv_bfloat162 t0, t1, u0, u1;
    t0.x = h[0]; t0.y = h[1]; t1.x = h[2]; t1.y = h[3];
    u0.x = l[0]; u0.y = l[1]; u1.x = l[2]; u1.y = l[3];
    *(__nv_bfloat162*)(g_xext + o)         = t0;
    *(__nv_bfloat162*)(g_xext + o + 2)     = t1;
    *(__nv_bfloat162*)(g_xext + o + 256)   = u0;
    *(__nv_bfloat162*)(g_xext + o + 258)   = u1;
}

__global__ void prep_B_kernel(
    const float* __restrict__ Wq, const float* __restrict__ Wk,
    const float* __restrict__ Wv, const float* __restrict__ Ws)
{
    int idx = blockIdx.x * blockDim.x + threadIdx.x;   // 256*800 threads
    if (idx >= INC * NFUSE) return;
    int kk = idx / NFUSE, n = idx % NFUSE;
    int m = n / HID, jj = n % HID;
    const float* W = (m == 0) ? Wq : (m == 1) ? Wk : (m == 2) ? Wv : Ws;
    float w = W[(size_t)kk * HID + jj];
    __nv_bfloat16 h = __float2bfloat16(w);
    __nv_bfloat16 l = __float2bfloat16(w - __bfloat162float(h));
    size_t base = (size_t)n * KEXT;
    g_Bt[base + kk]       = h;
    g_Bt[base + 256 + kk] = l;
    g_Bt[base + 512 + kk] = h;
}

// ---------------- HMMA GEMM: [Q1|K1|V1|S1](+bias) = A_ext @ B_ext^T -------------
#define GM 256
#define GN 160
#define GK 64
#define NITER (KEXT / GK)   // 12

#define ASTAGE 32768
#define BSTAGE 20480
#define NSTAGE 3
#define OFF_BIAS 0
#define OFF_A    1024
#define OFF_B    (1024 + NSTAGE * ASTAGE)
#define GSMEM_BYTES (OFF_B + NSTAGE * BSTAGE) // 160768

__device__ __forceinline__ uint32_t swz(int r, int c) {   // byte offset in a stage, c in 0..7
    return (uint32_t)(r * 128 + (((c ^ r) & 7) << 4) + ((c & ~7) << 4));
}

__global__ __launch_bounds__(512, 1) void gemm1_tc(
    const float* __restrict__ bq, const float* __restrict__ bk,
    const float* __restrict__ bv, const float* __restrict__ bs)
{
    extern __shared__ char smem[];
    const uint32_t sb = smem_u32(smem);
    const int tid  = threadIdx.x;
    const int wid  = tid >> 5;
    const int lane = tid & 31;
    const int warpm = wid & 3;
    const int warpn = wid >> 2;
    const int r0 = blockIdx.y * GM;
    const int c0 = blockIdx.x * GN;

    if (tid < GN) {
        int cg = c0 + tid;
        int m = cg / HID, jj = cg - m * HID;
        const float* bp = (m == 0) ? bq : (m == 1) ? bk : (m == 2) ? bv : bs;
        *(float*)(smem + OFF_BIAS + tid * 4) = bp[jj];
    }

    const int lr = tid >> 3, lc = tid & 7;
    const uint32_t sdA0 = swz(lr,       lc);
    const uint32_t sdA1 = swz(lr + 64,  lc);
    const uint32_t sdA2 = swz(lr + 128, lc);
    const uint32_t sdA3 = swz(lr + 192, lc);
    const uint32_t sdB0 = sdA0;
    const uint32_t sdB1 = sdA1;
    const uint32_t sdB2 = swz(lr + 128, lc);
    // row-base pointers (column added per stage)
    const __nv_bfloat16* aRow0 = g_xext + (size_t)(r0 + lr) * XCOLS + lc * 8;
    const __nv_bfloat16* aRow1 = aRow0 + (size_t)64  * XCOLS;
    const __nv_bfloat16* aRow2 = aRow0 + (size_t)128 * XCOLS;
    const __nv_bfloat16* aRow3 = aRow0 + (size_t)192 * XCOLS;
    const __nv_bfloat16* bRow0 = g_Bt + (size_t)(c0 + lr) * KEXT + lc * 8;
    const __nv_bfloat16* bRow1 = bRow0 + (size_t)64  * KEXT;
    const __nv_bfloat16* bRow2 = bRow0 + (size_t)128 * KEXT;   // deref only if tid<256

    auto load_stage = [&](int sidx, int it) {
        // A segments: it 0-3 -> hi, 4-7 -> hi, 8-11 -> lo(+256)
        const int acol = (it < 4) ? it * GK : (it < 8) ? (it - 4) * GK : 256 + (it - 8) * GK;
        const int bcol = it * GK;
        const uint32_t Ab = sb + OFF_A + sidx * ASTAGE;
        const uint32_t Bb = sb + OFF_B + sidx * BSTAGE;
        cpasync16(Ab + sdA0, aRow0 + acol);
        cpasync16(Ab + sdA1, aRow1 + acol);
        cpasync16(Ab + sdA2, aRow2 + acol);
        cpasync16(Ab + sdA3, aRow3 + acol);
        cpasync16(Bb + sdB0, bRow0 + bcol);
        cpasync16(Bb + sdB1, bRow1 + bcol);
        if (tid < 256) cpasync16(Bb + sdB2, bRow2 + bcol);
        CP_COMMIT();
    };

    float acc[4][5][4];
#pragma unroll
    for (int mt = 0; mt < 4; mt++)
#pragma unroll
        for (int nt = 0; nt < 5; nt++)
#pragma unroll
            for (int q = 0; q < 4; q++) acc[mt][nt][q] = 0.f;

    load_stage(0, 0);
    load_stage(1, 1);

    const int m0 = warpm * 64;
    const int n0 = warpn * 40;
    const int lrow = lane & 15;
    const int lchunk = lane >> 4;

    for (int j = 0; j < NITER; j += NSTAGE) {
#pragma unroll
        for (int s = 0; s < NSTAGE; s++) {
            const int i = j + s;
            if (i + 1 < NITER) { CP_WAIT(1); } else { CP_WAIT(0); }
            __syncthreads();
            if (i + 2 < NITER) load_stage((s + 2) % 3, i + 2);

            const uint32_t Ab = sb + OFF_A + s * ASTAGE;
            const uint32_t Bb = sb + OFF_B + s * BSTAGE;
#pragma unroll
            for (int kt = 0; kt < 4; kt++) {
                const int cbase = kt * 2 + lchunk;
                uint32_t a[4][4];
#pragma unroll
                for (int mt = 0; mt < 4; mt++)
                    ldmx4(a[mt][0], a[mt][1], a[mt][2], a[mt][3],
                          Ab + swz(m0 + mt * 16 + lrow, cbase));
                uint32_t b[5][2];
#pragma unroll
                for (int p = 0; p < 2; p++) {
                    uint32_t q0, q1, q2, q3;
                    ldmx4(q0, q1, q2, q3, Bb + swz(n0 + p * 16 + lrow, cbase));
                    b[2 * p][0] = q0; b[2 * p + 1][0] = q1;
                    b[2 * p][1] = q2; b[2 * p + 1][1] = q3;
                }
                ldmx2(b[4][0], b[4][1],
                      Bb + swz(n0 + 32 + (lane & 7), kt * 2 + ((lane >> 3) & 1)));
#pragma unroll
                for (int mt = 0; mt < 4; mt++)
#pragma unroll
                    for (int nt = 0; nt < 5; nt++)
                        mma16816(acc[mt][nt], a[mt], b[nt][0], b[nt][1]);
            }
        }
    }

    // ---- epilogue: fused bias; Q bf16 (pre-scaled), S fp32, K/V bf16 ----
    const float qscale = 0.0707106781186547f;  // 1/sqrt(200)
#pragma unroll
    for (int mt = 0; mt < 4; mt++) {
#pragma unroll
        for (int h = 0; h < 2; h++) {
            int gr = r0 + m0 + mt * 16 + h * 8 + (lane >> 2);
            if (gr >= NN) continue;
#pragma unroll
            for (int nt = 0; nt < 5; nt++) {
                int jl = n0 + nt * 8 + (lane & 3) * 2;
                int cg = c0 + jl;
                int m = cg / HID, jj = cg - m * HID;
                float2 bb = *(const float2*)(smem + OFF_BIAS + jl * 4);
                float2 v;
                v.x = acc[mt][nt][2 * h]     + bb.x;
                v.y = acc[mt][nt][2 * h + 1] + bb.y;
                if (m == 0) {
                    __nv_bfloat162 t;
                    t.x = __float2bfloat16(v.x * qscale);
                    t.y = __float2bfloat16(v.y * qscale);
                    *(__nv_bfloat162*)(g_Q1 + (size_t)gr * HID + jj) = t;
                } else if (m == 3) {
                    *(float2*)(g_S1 + (size_t)gr * HID + jj) = v;
                } else {
                    __nv_bfloat162 t;
                    t.x = __float2bfloat16(v.x);
                    t.y = __float2bfloat16(v.y);
                    int off = (m == 1) ? jj : 200 + jj;
                    *(__nv_bfloat162*)(g_KV1 + (size_t)gr * 400 + off) = t;
                }
            }
        }
    }
}

// ------- layer-1 edge aggregation + fused layer-2 projection (warp per dst) ----
__global__ __launch_bounds__(256) void edge1_kernel(
    const float* __restrict__ Wq, const float* __restrict__ bq,
    const float* __restrict__ Wk, const float* __restrict__ bk,
    const float* __restrict__ Wv, const float* __restrict__ bv,
    const float* __restrict__ Ws, const float* __restrict__ bs)
{
    __shared__ float ws[8][HID];   // transposed W2: ws[c][k]
    __shared__ float bb2[8];
    for (int l = threadIdx.x; l < HID * 8; l += blockDim.x) {
        int c = l / HID, k = l - c * HID;
        int w = c >> 1, j = c & 1;
        const float* W = (w == 0) ? Wq : (w == 1) ? Wk : (w == 2) ? Wv : Ws;
        ws[c][k] = W[k * 2 + j];
    }
    if (threadIdx.x < 8) {
        int c = threadIdx.x, w = c >> 1, j = c & 1;
        const float* B = (w == 0) ? bq : (w == 1) ? bk : (w == 2) ? bv : bs;
        bb2[c] = B[j];
    }
    __syncthreads();

    int warp = blockIdx.x * 8 + (threadIdx.x >> 5);
    int lane = threadIdx.x & 31;
    if (warp >= NN) return;

    const int e0 = g_rowptr[warp];
    const int e1 = g_rowptr[warp + 1];

    float2 q[4];
    const __nv_bfloat162* qp = (const __nv_bfloat162*)(g_Q1 + (size_t)warp * HID);
#pragma unroll
    for (int r = 0; r < 4; r++) {
        int idx = lane + 32 * r;
        q[r] = (idx < 100) ? __bfloat1622float2(qp[idx]) : make_float2(0.f, 0.f);
    }

    float2 acc[4];
#pragma unroll
    for (int r = 0; r < 4; r++) { acc[r].x = 0.f; acc[r].y = 0.f; }
    float m = __int_as_float(0xff800000);
    float s = 0.f;

    int e = e0;
    for (; e + 4 <= e1; e += 4) {
        int si[4];
#pragma unroll
        for (int t = 0; t < 4; t++) si[t] = g_csrc[e + t];
        float2 kk[4][4], vv[4][4];
#pragma unroll
        for (int t = 0; t < 4; t++) {
            const __nv_bfloat162* p = (const __nv_bfloat162*)(g_KV1 + (size_t)si[t] * 400);
#pragma unroll
            for (int r = 0; r < 4; r++) {
                int idx = lane + 32 * r;
                bool ok = (idx < 100);
                kk[t][r] = ok ? __bfloat1622float2(p[idx])       : make_float2(0.f, 0.f);
                vv[t][r] = ok ? __bfloat1622float2(p[100 + idx]) : make_float2(0.f, 0.f);
            }
        }
        float p4[4];
#pragma unroll
        for (int t = 0; t < 4; t++) {
            float d = 0.f;
#pragma unroll
            for (int r = 0; r < 4; r++) d += q[r].x * kk[t][r].x + q[r].y * kk[t][r].y;
            p4[t] = d;
        }
#pragma unroll
        for (int off = 16; off > 0; off >>= 1)
#pragma unroll
            for (int t = 0; t < 4; t++)
                p4[t] += __shfl_xor_sync(0xffffffffu, p4[t], off);

        float mx = fmaxf(fmaxf(p4[0], p4[1]), fmaxf(p4[2], p4[3]));
        float mn = fmaxf(m, mx);
        float c = __expf(m - mn);
        float w[4];
#pragma unroll
        for (int t = 0; t < 4; t++) w[t] = __expf(p4[t] - mn);
        s = s * c + w[0] + w[1] + w[2] + w[3];
#pragma unroll
        for (int r = 0; r < 4; r++) {
            float ax = acc[r].x * c, ay = acc[r].y * c;
#pragma unroll
            for (int t = 0; t < 4; t++) { ax += w[t] * vv[t][r].x; ay += w[t] * vv[t][r].y; }
            acc[r].x = ax; acc[r].y = ay;
        }
        m = mn;
    }
    for (; e < e1; e++) {
        int src = g_csrc[e];
        const __nv_bfloat162* kvp = (const __nv_bfloat162*)(g_KV1 + (size_t)src * 400);
        float2 kv[4], vv[4];
#pragma unroll
        for (int r = 0; r < 4; r++) {
            int idx = lane + 32 * r;
            bool ok = (idx < 100);
            kv[r] = ok ? __bfloat1622float2(kvp[idx])       : make_float2(0.f, 0.f);
            vv[r] = ok ? __bfloat1622float2(kvp[100 + idx]) : make_float2(0.f, 0.f);
        }
        float p = 0.f;
#pragma unroll
        for (int r = 0; r < 4; r++) p += q[r].x * kv[r].x + q[r].y * kv[r].y;
#pragma unroll
        for (int off = 16; off > 0; off >>= 1)
            p += __shfl_xor_sync(0xffffffffu, p, off);
        float mn = fmaxf(m, p);
        float c = __expf(m - mn);
        float w = __expf(p - mn);
        s = s * c + w;
#pragma unroll
        for (int r = 0; r < 4; r++) {
            acc[r].x = acc[r].x * c + w * vv[r].x;
            acc[r].y = acc[r].y * c + w * vv[r].y;
        }
        m = mn;
    }

    // ---- epilogue: h = relu(agg/s + skip) in registers, then project to 8 outs --
    float inv = (e1 > e0) ? (1.f / s) : 0.f;
    float a2[8];
#pragma unroll
    for (int c = 0; c < 8; c++) a2[c] = 0.f;
#pragma unroll
    for (int r = 0; r < 4; r++) {
        int idx = lane + 32 * r;
        if (idx < 100) {
            float2 sk = ((const float2*)(g_S1 + (size_t)warp * HID))[idx];
            float hx = acc[r].x * inv + sk.x;
            float hy = acc[r].y * inv + sk.y;
            hx = hx > 0.f ? hx : 0.f;
            hy = hy > 0.f ? hy : 0.f;
            int d0 = idx * 2;
#pragma unroll
            for (int c = 0; c < 8; c++)
                a2[c] += hx * ws[c][d0] + hy * ws[c][d0 + 1];
        }
    }
#pragma unroll
    for (int off = 16; off > 0; off >>= 1)
#pragma unroll
        for (int c = 0; c < 8; c++)
            a2[c] += __shfl_xor_sync(0xffffffffu, a2[c], off);

    if (lane == 0) {
        float4 o0, o1;
        o0.x = a2[0] + bb2[0]; o0.y = a2[1] + bb2[1]; o0.z = a2[2] + bb2[2]; o0.w = a2[3] + bb2[3];
        o1.x = a2[4] + bb2[4]; o1.y = a2[5] + bb2[5]; o1.z = a2[6] + bb2[6]; o1.w = a2[7] + bb2[7];
        *(float4*)(g_b2 + (size_t)warp * 8)     = o0;
        *(float4*)(g_b2 + (size_t)warp * 8 + 4) = o1;
    }
}

// ---------------- layer-2 edge aggregation ----------------
__global__ __launch_bounds__(256) void edge2_kernel(float* __restrict__ out) {
    int i = blockIdx.x * blockDim.x + threadIdx.x;
    if (i >= NN) return;
    const int e0 = g_rowptr[i];
    const int e1 = g_rowptr[i + 1];
    const float scale = 0.7071067811865475f;
    const float* me = g_b2 + (size_t)i * 8;
    float q0 = me[0] * scale, q1 = me[1] * scale;
    float m = __int_as_float(0xff800000);
    float s = 0.f, a0 = 0.f, a1 = 0.f;
    for (int e = e0; e < e1; e++) {
        int src = g_csrc[e];
        const float* p = g_b2 + (size_t)src * 8;
        float k0 = p[2], k1 = p[3], v0 = p[4], v1 = p[5];
        float sc = q0 * k0 + q1 * k1;
        float mn = fmaxf(m, sc);
        float c = __expf(m - mn);
        float w = __expf(sc - mn);
        s = s * c + w;
        a0 = a0 * c + w * v0;
        a1 = a1 * c + w * v1;
        m = mn;
    }
    float inv = (e1 > e0) ? (1.f / s) : 0.f;
    float o0 = a0 * inv + me[6];
    float o1 = a1 * inv + me[7];
    out[(size_t)i * 2 + 0] = o0 > 0.f ? o0 : 0.f;
    out[(size_t)i * 2 + 1] = o1 > 0.f ? o1 : 0.f;
}

// ---------------- launch: forked graph (prep_B + CSR chain || prep_x + gemm) ---
extern "C" void kernel_launch(void* const* d_in, const int* in_sizes, int n_in,
                              void* d_out, int out_size) {
    const float* x   = (const float*)d_in[0];
    const int*   ei  = (const int*)d_in[1];
    const float *Wq1 = (const float*)d_in[2],  *bq1 = (const float*)d_in[3];
    const float *Wk1 = (const float*)d_in[4],  *bk1 = (const float*)d_in[5];
    const float *Wv1 = (const float*)d_in[6],  *bv1 = (const float*)d_in[7];
    const float *Ws1 = (const float*)d_in[8],  *bs1 = (const float*)d_in[9];
    const float *Wq2 = (const float*)d_in[10], *bq2 = (const float*)d_in[11];
    const float *Wk2 = (const float*)d_in[12], *bk2 = (const float*)d_in[13];
    const float *Wv2 = (const float*)d_in[14], *bv2 = (const float*)d_in[15];
    const float *Ws2 = (const float*)d_in[16], *bs2 = (const float*)d_in[17];
    float* out = (float*)d_out;

    // one-time creation (first, uncaptured correctness call); reused thereafter
    static cudaStream_t s2 = nullptr;
    static cudaEvent_t evFork = nullptr, evJoin = nullptr, evB = nullptr;
    if (s2 == nullptr) {
        cudaStreamCreateWithFlags(&s2, cudaStreamNonBlocking);
        cudaEventCreateWithFlags(&evFork, cudaEventDisableTiming);
        cudaEventCreateWithFlags(&evJoin, cudaEventDisableTiming);
        cudaEventCreateWithFlags(&evB, cudaEventDisableTiming);
        cudaFuncSetAttribute(gemm1_tc, cudaFuncAttributeMaxDynamicSharedMemorySize, GSMEM_BYTES);
    }

    // fork: branch B (prep_B + CSR build) on s2
    cudaEventRecord(evFork, 0);
    cudaStreamWaitEvent(s2, evFork, 0);

    prep_B_kernel<<<(INC * NFUSE + 255) / 256, 256, 0, s2>>>(Wq1, Wk1, Wv1, Ws1);
    cudaEventRecord(evB, s2);                 // gemm needs g_Bt
    zero_deg_kernel<<<(NN + 255) / 256, 256, 0, s2>>>();
    count_kernel<<<(EE + 255) / 256, 256, 0, s2>>>(ei);
    scan1_kernel<<<SCAN_BLOCKS, 256, 0, s2>>>();
    scan2_kernel<<<1, 256, 0, s2>>>();
    scan3_kernel<<<SCAN_BLOCKS, 256, 0, s2>>>();
    scatter_kernel<<<(EE + 255) / 256, 256, 0, s2>>>(ei);
    cudaEventRecord(evJoin, s2);

    // branch A: prep_x + gemm on default stream
    prep_x_kernel<<<(NPAD * 64 + 255) / 256, 256>>>(x);
    cudaStreamWaitEvent(0, evB, 0);           // wait for g_Bt
    dim3 g1(NFUSE / GN, NPAD / GM);   // (5, 196)
    gemm1_tc<<<g1, 512, GSMEM_BYTES>>>(bq1, bk1, bv1, bs1);

    // join: edge1 needs both gemm (stream order) and CSR (event)
    cudaStreamWaitEvent(0, evJoin, 0);

    edge1_kernel<<<(NN * 32 + 255) / 256, 256>>>(Wq2, bq2, Wk2, bk2, Wv2, bv2, Ws2, bs2);
    edge2_kernel<<<(NN + 255) / 256, 256>>>(out);
}